// round 7
// baseline (speedup 1.0000x reference)
#include <cuda_runtime.h>
#include <math.h>
#include <stdint.h>

#define NN 10000
#define KK 16
#define EE (NN*KK)
#define HH 100
#define NB 10
#define NBP 16

// ---------------- scratch ----------------
__device__ float g_basis[EE*NBP];
__device__ float g_u[EE*3];
__device__ float g_h1[EE*HH];
__device__ float g_h2[EE*HH];
__device__ float g_f0a[NN*32];
__device__ float g_f0b[NN*32];
__device__ float g_f1a[NN*24];
__device__ float g_f1b[NN*24];
__device__ float g_w1t[NBP*HH];
__device__ float g_w2t[HH*HH];
__device__ float g_w3t[HH*832];

// ---------------- helpers ----------------
__device__ __forceinline__ float f2tf32f(float v) {
    uint32_t r;
    asm("cvt.rna.tf32.f32 %0, %1;" : "=r"(r) : "f"(v));
    return __uint_as_float(r);
}

__device__ __forceinline__ void mma_tf32(float* c, const uint32_t* a, const uint32_t* b) {
    asm volatile("mma.sync.aligned.m16n8k8.row.col.f32.tf32.tf32.f32 "
        "{%0,%1,%2,%3}, {%4,%5,%6,%7}, {%8,%9}, {%0,%1,%2,%3};"
        : "+f"(c[0]), "+f"(c[1]), "+f"(c[2]), "+f"(c[3])
        : "r"(a[0]), "r"(a[1]), "r"(a[2]), "r"(a[3]), "r"(b[0]), "r"(b[1]));
}

__device__ __forceinline__ void cp16(void* dst_smem, const void* src, int bytes) {
    uint32_t d = (uint32_t)__cvta_generic_to_shared(dst_smem);
    asm volatile("cp.async.cg.shared.global [%0], [%1], 16, %2;"
                 :: "r"(d), "l"(src), "r"(bytes));
}

// ---------------- prep ----------------
__global__ void prep_kernel(const float* __restrict__ radii) {
    int e = blockIdx.x*blockDim.x + threadIdx.x;
    if (e >= EE) return;
    float x = radii[e*3+0], y = radii[e*3+1], z = radii[e*3+2];
    float r = sqrtf(x*x + y*y + z*z);
    float inv = 1.0f / (r + 1e-8f);
    g_u[e*3+0] = x*inv; g_u[e*3+1] = y*inv; g_u[e*3+2] = z*inv;
    float rs = r * 1.8f;
    #pragma unroll
    for (int b = 0; b < NBP; b++) {
        float v = 0.f;
        if (b < NB) {
            float d = rs - (float)b;
            if (fabsf(d) < 1.0f) {
                float c = cospif(0.5f * d);
                v = f2tf32f(c * c);
            }
        }
        g_basis[e*NBP + b] = v;
    }
}

// ---------------- weight pre-round ----------------
__global__ void cvt_kernel(const float* __restrict__ src, float* __restrict__ dst, int n) {
    int i = blockIdx.x*blockDim.x + threadIdx.x;
    if (i < n) dst[i] = f2tf32f(src[i]);
}
__global__ void cvt_pad_kernel(const float* __restrict__ src, float* __restrict__ dst) {
    int i = blockIdx.x*blockDim.x + threadIdx.x;
    if (i >= NBP*HH) return;
    int row = i / HH;
    dst[i] = (row < NB) ? f2tf32f(src[i]) : 0.f;
}

// ---------------- tf32 GEMM for the radial MLP (unchanged, round-6 verified) ----------------
#define AS_STRIDE 36
#define BS_STRIDE 136
#define AS_BUF (128*AS_STRIDE)
#define BS_BUF (32*BS_STRIDE)
#define SMEM_FLOATS (2*AS_BUF + 2*BS_BUF)

template<bool RELU, bool CVTOUT>
__global__ void __launch_bounds__(256, 2)
gemm_tc(const float* __restrict__ A, const float* __restrict__ B,
        const float* __restrict__ bias, float* __restrict__ C,
        int M, int N, int K) {
    extern __shared__ float smem[];
    float* As = smem;
    float* Bs = smem + 2*AS_BUF;

    const int tid = threadIdx.x;
    const int lane = tid & 31, wid = tid >> 5;
    const int wm = (wid & 1) * 64;
    const int wn = (wid >> 1) * 32;
    const int m0 = blockIdx.y * 128, n0 = blockIdx.x * 128;
    const int gr = lane >> 2, tg = lane & 3;

    float acc[4][4][4] = {};
    const int ntiles = (K + 31) >> 5;

    auto load_tile = [&](int t, int buf) {
        int kc = t << 5;
        float* Ad = As + buf*AS_BUF;
        #pragma unroll
        for (int j = 0; j < 4; j++) {
            int c = tid + j*256;
            int row = c >> 3, kch = (c & 7) * 4;
            int gk = kc + kch;
            int bytes = (K - gk) * 4;
            bytes = bytes < 0 ? 0 : (bytes > 16 ? 16 : bytes);
            const float* src = bytes ? (A + (size_t)(m0+row)*K + gk) : A;
            cp16(Ad + row*AS_STRIDE + kch, src, bytes);
        }
        float* Bd = Bs + buf*BS_BUF;
        #pragma unroll
        for (int j = 0; j < 4; j++) {
            int c = tid + j*256;
            int k = c >> 5, nch = (c & 31) * 4;
            int gk = kc + k;
            int bytes = 0;
            if (gk < K) {
                bytes = (N - (n0 + nch)) * 4;
                bytes = bytes < 0 ? 0 : (bytes > 16 ? 16 : bytes);
            }
            const float* src = bytes ? (B + (size_t)gk*N + n0 + nch) : B;
            cp16(Bd + k*BS_STRIDE + nch, src, bytes);
        }
        asm volatile("cp.async.commit_group;");
    };

    load_tile(0, 0);

    for (int t = 0; t < ntiles; t++) {
        if (t + 1 < ntiles) {
            load_tile(t + 1, (t + 1) & 1);
            asm volatile("cp.async.wait_group 1;");
        } else {
            asm volatile("cp.async.wait_group 0;");
        }
        __syncthreads();
        const float* Ab = As + (t & 1)*AS_BUF;
        const float* Bb = Bs + (t & 1)*BS_BUF;
        #pragma unroll
        for (int k8 = 0; k8 < 4; k8++) {
            int k0 = k8 * 8;
            uint32_t a[4][4], b[4][2];
            #pragma unroll
            for (int t2 = 0; t2 < 4; t2++) {
                int row = wm + t2*16 + gr;
                a[t2][0] = __float_as_uint(Ab[row*AS_STRIDE     + k0 + tg]);
                a[t2][1] = __float_as_uint(Ab[(row+8)*AS_STRIDE + k0 + tg]);
                a[t2][2] = __float_as_uint(Ab[row*AS_STRIDE     + k0 + 4 + tg]);
                a[t2][3] = __float_as_uint(Ab[(row+8)*AS_STRIDE + k0 + 4 + tg]);
            }
            #pragma unroll
            for (int j = 0; j < 4; j++) {
                int col = wn + j*8 + gr;
                b[j][0] = __float_as_uint(Bb[(k0 + tg)*BS_STRIDE     + col]);
                b[j][1] = __float_as_uint(Bb[(k0 + 4 + tg)*BS_STRIDE + col]);
            }
            #pragma unroll
            for (int t2 = 0; t2 < 4; t2++)
                #pragma unroll
                for (int j = 0; j < 4; j++)
                    mma_tf32(acc[t2][j], a[t2], b[j]);
        }
        __syncthreads();
    }

    #pragma unroll
    for (int t2 = 0; t2 < 4; t2++) {
        #pragma unroll
        for (int j = 0; j < 4; j++) {
            int row = m0 + wm + t2*16 + gr;
            int col = n0 + wn + j*8 + tg*2;
            #pragma unroll
            for (int h = 0; h < 2; h++) {
                int r = row + h*8;
                #pragma unroll
                for (int q = 0; q < 2; q++) {
                    int cn = col + q;
                    if (cn < N) {
                        float v = acc[t2][j][h*2 + q];
                        if (bias) v += bias[cn];
                        if (RELU) v = fmaxf(v, 0.f);
                        if (CVTOUT) v = f2tf32f(v);
                        C[(size_t)r*N + cn] = v;
                    }
                }
            }
        }
    }
}

// ---------------- fused W-GEMM + tensor product + scatter-mean + gating ----------------
// One CTA = 128 edges = 8 nodes. W = h2 @ w3 computed in 128x64 chunks via mma.sync,
// spilled to smem, contracted immediately. W never hits DRAM.
// smem floats: As 2*128*36=9216 | Bs 2*32*68=4352 | Wc 128*65=8320 | g0 2048 | g1 3072 | p 1024
#define FAS 36
#define FBS 68
#define FAB (128*FAS)
#define FBB (32*FBS)
#define F_SMEM_FLOATS (2*FAB + 2*FBB + 128*65 + 2048 + 3072 + 1024)

template<int LAYER>
__global__ void __launch_bounds__(256, 2)
fused_tp(const int* __restrict__ nbr, const int* __restrict__ charges,
         const float* __restrict__ h2, const float* __restrict__ w3t) {
    constexpr int M0I = (LAYER==1) ? 1 : 16;
    constexpr int M1I = (LAYER==1) ? 0 : 8;
    constexpr int M0O = (LAYER==3) ? 32 : 16;
    constexpr int NG  = (LAYER==3) ? 0 : 8;
    constexpr int M1O = (LAYER==3) ? 0 : 8;
    constexpr int M0T = M0O + NG;
    constexpr int OFF1 = M0T*M0I;
    constexpr int OFF2 = OFF1 + M0T*M1I;
    constexpr int OFF3 = OFF2 + M1O*M0I;
    constexpr int OFF4 = OFF3 + M1O*M1I;
    constexpr int WTOT = OFF4 + M1O*M1I;
    constexpr int NCHUNK = (WTOT + 63) / 64;
    constexpr int T = NCHUNK * 4;
    constexpr int NS = (LAYER==3) ? 16 : 32;

    extern __shared__ float sm[];
    float* As  = sm;
    float* Bs  = sm + 2*FAB;
    float* Wc  = sm + 2*FAB + 2*FBB;
    float* g0s = Wc + 128*65;
    float* g1s = g0s + 2048;
    float* psh = g1s + 3072;

    const int tid = threadIdx.x, lane = tid & 31, wid = tid >> 5;
    const int e0 = blockIdx.x * 128;
    const int el = tid >> 1, hh = tid & 1;

    const float* __restrict__ f0in = (LAYER==2) ? g_f0a : g_f0b;
    const float* __restrict__ f1in = (LAYER==2) ? g_f1a : g_f1b;
    float* f0out = (LAYER==2) ? g_f0b : g_f0a;
    float* f1out = (LAYER==2) ? g_f1b : g_f1a;

    // ---- gather features ----
    float u0 = 0.f, u1 = 0.f, u2 = 0.f;
    {
        int idx = nbr[e0 + el];
        if (hh == 0) {
            if (LAYER == 1) {
                g0s[el*16] = 0.5f * ((float)charges[idx] / 94.0f - 0.5f);
            } else {
                #pragma unroll
                for (int i = 0; i < 16; i++) g0s[el*16 + i] = 0.5f * f0in[idx*16 + i];
            }
        } else {
            u0 = g_u[(e0+el)*3+0]; u1 = g_u[(e0+el)*3+1]; u2 = g_u[(e0+el)*3+2];
            if (M1I > 0) {
                #pragma unroll
                for (int i = 0; i < 8; i++) {
                    float a = 0.5f * f1in[idx*24 + 3*i + 0];
                    float b = 0.5f * f1in[idx*24 + 3*i + 1];
                    float c = 0.5f * f1in[idx*24 + 3*i + 2];
                    if (LAYER == 2) {
                        g1s[el*24 + 3*i + 0] = a;
                        g1s[el*24 + 3*i + 1] = b;
                        g1s[el*24 + 3*i + 2] = c;
                    }
                    psh[el*8 + i] = a*u0 + b*u1 + c*u2;
                }
            }
        }
    }
    __syncthreads();

    // ---- pipelined chunked mma + immediate TP contraction ----
    const int wm = (wid & 3) * 32, wn = (wid >> 2) * 32;
    const int gr = lane >> 2, tg = lane & 3;

    float acc[2][4][4] = {};
    float atp[32];
    #pragma unroll
    for (int s = 0; s < 32; s++) atp[s] = 0.f;

    auto load_tile = [&](int tt, int buf) {
        int kc = (tt & 3) << 5;
        int n0c = (tt >> 2) << 6;
        float* Ad = As + buf*FAB;
        #pragma unroll
        for (int j = 0; j < 4; j++) {
            int c = tid + j*256;
            int row = c >> 3, kch = (c & 7) * 4;
            int gk = kc + kch;
            int bytes = (HH - gk) * 4;
            bytes = bytes < 0 ? 0 : (bytes > 16 ? 16 : bytes);
            const float* src = bytes ? (h2 + (size_t)(e0+row)*HH + gk) : h2;
            cp16(Ad + row*FAS + kch, src, bytes);
        }
        float* Bd = Bs + buf*FBB;
        #pragma unroll
        for (int j = 0; j < 2; j++) {
            int c = tid + j*256;
            int k = c >> 4, nch = (c & 15) * 4;
            int gk = kc + k;
            int bytes = 0;
            if (gk < HH) {
                bytes = (WTOT - (n0c + nch)) * 4;
                bytes = bytes < 0 ? 0 : (bytes > 16 ? 16 : bytes);
            }
            const float* src = bytes ? (w3t + (size_t)gk*WTOT + n0c + nch) : w3t;
            cp16(Bd + k*FBS + nch, src, bytes);
        }
        asm volatile("cp.async.commit_group;");
    };

    load_tile(0, 0);

    for (int tt = 0; tt < T; tt++) {
        if (tt + 1 < T) {
            load_tile(tt + 1, (tt + 1) & 1);
            asm volatile("cp.async.wait_group 1;");
        } else {
            asm volatile("cp.async.wait_group 0;");
        }
        __syncthreads();

        const float* Ab = As + (tt & 1)*FAB;
        const float* Bb = Bs + (tt & 1)*FBB;
        #pragma unroll
        for (int k8 = 0; k8 < 4; k8++) {
            int k0 = k8 * 8;
            uint32_t a[2][4], b[4][2];
            #pragma unroll
            for (int t2 = 0; t2 < 2; t2++) {
                int row = wm + t2*16 + gr;
                a[t2][0] = __float_as_uint(Ab[row*FAS     + k0 + tg]);
                a[t2][1] = __float_as_uint(Ab[(row+8)*FAS + k0 + tg]);
                a[t2][2] = __float_as_uint(Ab[row*FAS     + k0 + 4 + tg]);
                a[t2][3] = __float_as_uint(Ab[(row+8)*FAS + k0 + 4 + tg]);
            }
            #pragma unroll
            for (int j = 0; j < 4; j++) {
                int col = wn + j*8 + gr;
                b[j][0] = __float_as_uint(Bb[(k0 + tg)*FBS     + col]);
                b[j][1] = __float_as_uint(Bb[(k0 + 4 + tg)*FBS + col]);
            }
            #pragma unroll
            for (int t2 = 0; t2 < 2; t2++)
                #pragma unroll
                for (int j = 0; j < 4; j++)
                    mma_tf32(acc[t2][j], a[t2], b[j]);
        }

        if ((tt & 3) == 3) {
            // spill W chunk to smem
            __syncthreads();
            #pragma unroll
            for (int t2 = 0; t2 < 2; t2++)
                #pragma unroll
                for (int j = 0; j < 4; j++)
                    #pragma unroll
                    for (int h = 0; h < 2; h++)
                        #pragma unroll
                        for (int q = 0; q < 2; q++)
                            Wc[(wm + t2*16 + gr + 8*h)*65 + wn + j*8 + tg*2 + q]
                                = acc[t2][j][h*2 + q];
            #pragma unroll
            for (int t2 = 0; t2 < 2; t2++)
                #pragma unroll
                for (int j = 0; j < 4; j++)
                    #pragma unroll
                    for (int q = 0; q < 4; q++) acc[t2][j][q] = 0.f;
            __syncthreads();

            // TP contraction for this chunk
            int c = tt >> 2;
            int j0 = c * 64, j1 = j0 + 64;
            const float* wrow = Wc + el*65 - j0;

            if (hh == 0) {
                {   // 0->0 scalar block (L3: only o<16)
                    constexpr int end0 = (LAYER==3) ? 16*M0I : OFF1;
                    int lo = j0 > 0 ? j0 : 0, hi = j1 < end0 ? j1 : end0;
                    for (int j = lo; j < hi; j++) {
                        int o = j / M0I, i = j - o*M0I;
                        atp[o] += wrow[j] * g0s[el*16 + i];
                    }
                }
                if (M1I > 0) {   // 1->0 block (L3: only o<16)
                    constexpr int end1 = OFF1 + ((LAYER==3) ? 16*M1I : M0T*M1I);
                    int lo = j0 > OFF1 ? j0 : OFF1, hi = j1 < end1 ? j1 : end1;
                    for (int j = lo; j < hi; j++) {
                        int jj = j - OFF1;
                        int o = jj / M1I, i = jj - o*M1I;
                        atp[o] += wrow[j] * psh[el*8 + i];
                    }
                }
            } else {
                if (LAYER == 3) {
                    {   // 0->0, o>=16
                        int lo = j0 > 16*M0I ? j0 : 16*M0I, hi = j1 < OFF1 ? j1 : OFF1;
                        for (int j = lo; j < hi; j++) {
                            int o = j / M0I, i = j - o*M0I;
                            atp[o-16] += wrow[j] * g0s[el*16 + i];
                        }
                    }
                    {   // 1->0, o>=16
                        constexpr int st = OFF1 + 16*M1I;
                        int lo = j0 > st ? j0 : st, hi = j1 < OFF2 ? j1 : OFF2;
                        for (int j = lo; j < hi; j++) {
                            int jj = j - OFF1;
                            int o = jj / M1I, i = jj - o*M1I;
                            atp[o-16] += wrow[j] * psh[el*8 + i];
                        }
                    }
                } else {
                    {   // 0->1: dot accumulators
                        int lo = j0 > OFF2 ? j0 : OFF2, hi = j1 < OFF3 ? j1 : OFF3;
                        for (int j = lo; j < hi; j++) {
                            int jj = j - OFF2;
                            int o = jj / M0I, i = jj - o*M0I;
                            atp[o] += wrow[j] * g0s[el*16 + i];
                        }
                    }
                    if (M1I > 0) {
                        {   // 1->1 (l_f=0): v += W * g1
                            int lo = j0 > OFF3 ? j0 : OFF3, hi = j1 < OFF4 ? j1 : OFF4;
                            for (int j = lo; j < hi; j++) {
                                int jj = j - OFF3;
                                int o = jj / M1I, i = jj - o*M1I;
                                float wv = wrow[j];
                                atp[8 + o*3 + 0] += wv * g1s[el*24 + 3*i + 0];
                                atp[8 + o*3 + 1] += wv * g1s[el*24 + 3*i + 1];
                                atp[8 + o*3 + 2] += wv * g1s[el*24 + 3*i + 2];
                            }
                        }
                        {   // 1->1 (l_f=1): v += W * cross(g1, u)
                            int lo = j0 > OFF4 ? j0 : OFF4, hi = j1 < WTOT ? j1 : WTOT;
                            for (int j = lo; j < hi; j++) {
                                int jj = j - OFF4;
                                int o = jj / M1I, i = jj - o*M1I;
                                float wv = wrow[j];
                                float a = g1s[el*24 + 3*i + 0];
                                float b = g1s[el*24 + 3*i + 1];
                                float cc = g1s[el*24 + 3*i + 2];
                                atp[8 + o*3 + 0] += wv * (b*u2 - cc*u1);
                                atp[8 + o*3 + 1] += wv * (cc*u0 - a*u2);
                                atp[8 + o*3 + 2] += wv * (a*u1 - b*u0);
                            }
                        }
                    }
                }
            }
        } else {
            __syncthreads();
        }
    }

    // ---- per-edge dot -> vector, then warp reduction over 16 edges ----
    if (LAYER != 3 && hh == 1) {
        #pragma unroll
        for (int o = 0; o < 8; o++) {
            atp[8 + o*3 + 0] += atp[o] * u0;
            atp[8 + o*3 + 1] += atp[o] * u1;
            atp[8 + o*3 + 2] += atp[o] * u2;
        }
    }
    __syncwarp();
    #pragma unroll
    for (int s = 0; s < NS; s++) {
        atp[s] += __shfl_xor_sync(0xffffffffu, atp[s], 2);
        atp[s] += __shfl_xor_sync(0xffffffffu, atp[s], 4);
        atp[s] += __shfl_xor_sync(0xffffffffu, atp[s], 8);
        atp[s] += __shfl_xor_sync(0xffffffffu, atp[s], 16);
    }

    int n = blockIdx.x * 8 + wid;
    if (LAYER == 3) {
        if (lane == 0) {
            #pragma unroll
            for (int o = 0; o < 16; o++)
                f0out[n*32 + o] = fmaxf(atp[o] * (1.0f/16.0f), 0.f);
        } else if (lane == 1) {
            #pragma unroll
            for (int o = 0; o < 16; o++)
                f0out[n*32 + 16 + o] = fmaxf(atp[o] * (1.0f/16.0f), 0.f);
        }
    } else {
        if (lane == 0) {
            #pragma unroll
            for (int o = 0; o < 16; o++)
                f0out[n*16 + o] = fmaxf(atp[o] * (1.0f/16.0f), 0.f);
        }
        float graw[8];
        #pragma unroll
        for (int o = 0; o < 8; o++)
            graw[o] = __shfl_sync(0xffffffffu, atp[16 + o], lane & 30);
        if (lane == 1) {
            #pragma unroll
            for (int o = 0; o < 8; o++) {
                float gate = 1.0f / (1.0f + expf(-graw[o] * (1.0f/16.0f)));
                #pragma unroll
                for (int cc = 0; cc < 3; cc++)
                    f1out[(n*8 + o)*3 + cc] = atp[8 + o*3 + cc] * (1.0f/16.0f) * gate;
            }
        }
    }
}

// ---------------- final reduce ----------------
__global__ void reduce_kernel(float* __restrict__ out) {
    __shared__ float red[256];
    int j = blockIdx.x;
    float s = 0.f;
    for (int n = threadIdx.x; n < NN; n += 256) s += g_f0a[n*32 + j];
    red[threadIdx.x] = s;
    __syncthreads();
    for (int w = 128; w > 0; w >>= 1) {
        if (threadIdx.x < w) red[threadIdx.x] += red[threadIdx.x + w];
        __syncthreads();
    }
    if (threadIdx.x == 0) out[j] = red[0] * (1.0f/NN);
}

// ---------------- host ----------------
extern "C" void kernel_launch(void* const* d_in, const int* in_sizes, int n_in,
                              void* d_out, int out_size) {
    const float* radii   = (const float*)d_in[0];
    const int*   nbr     = (const int*)d_in[1];
    const int*   charges = (const int*)d_in[2];

    void* p;
    cudaGetSymbolAddress(&p, g_basis); float* basis = (float*)p;
    cudaGetSymbolAddress(&p, g_h1);    float* h1    = (float*)p;
    cudaGetSymbolAddress(&p, g_h2);    float* h2    = (float*)p;
    cudaGetSymbolAddress(&p, g_w1t);   float* w1t   = (float*)p;
    cudaGetSymbolAddress(&p, g_w2t);   float* w2t   = (float*)p;
    cudaGetSymbolAddress(&p, g_w3t);   float* w3t   = (float*)p;

    const int smem_bytes = SMEM_FLOATS * 4;       // 71680
    const int fsm_bytes  = F_SMEM_FLOATS * 4;     // 112128
    cudaFuncSetAttribute(gemm_tc<true , true >, cudaFuncAttributeMaxDynamicSharedMemorySize, smem_bytes);
    cudaFuncSetAttribute(fused_tp<1>, cudaFuncAttributeMaxDynamicSharedMemorySize, fsm_bytes);
    cudaFuncSetAttribute(fused_tp<2>, cudaFuncAttributeMaxDynamicSharedMemorySize, fsm_bytes);
    cudaFuncSetAttribute(fused_tp<3>, cudaFuncAttributeMaxDynamicSharedMemorySize, fsm_bytes);

    prep_kernel<<<(EE+255)/256, 256>>>(radii);

    const int wtot[3] = {32, 832, 768};
    for (int l = 0; l < 3; l++) {
        const float* w1 = (const float*)d_in[3 + 5*l + 0];
        const float* b1 = (const float*)d_in[3 + 5*l + 1];
        const float* w2 = (const float*)d_in[3 + 5*l + 2];
        const float* b2 = (const float*)d_in[3 + 5*l + 3];
        const float* w3 = (const float*)d_in[3 + 5*l + 4];

        cvt_pad_kernel<<<(NBP*HH+255)/256, 256>>>(w1, w1t);
        cvt_kernel<<<(HH*HH+255)/256, 256>>>(w2, w2t, HH*HH);
        cvt_kernel<<<(HH*wtot[l]+255)/256, 256>>>(w3, w3t, HH*wtot[l]);

        dim3 gridH(1, EE/128);
        gemm_tc<true, true><<<gridH, 256, smem_bytes>>>(basis, w1t, b1, h1, EE, HH, NBP);
        gemm_tc<true, true><<<gridH, 256, smem_bytes>>>(h1,    w2t, b2, h2, EE, HH, HH);

        if      (l == 0) fused_tp<1><<<EE/128, 256, fsm_bytes>>>(nbr, charges, h2, w3t);
        else if (l == 1) fused_tp<2><<<EE/128, 256, fsm_bytes>>>(nbr, charges, h2, w3t);
        else             fused_tp<3><<<EE/128, 256, fsm_bytes>>>(nbr, charges, h2, w3t);
    }
    reduce_kernel<<<32, 256>>>((float*)d_out);
}

// round 8
// speedup vs baseline: 1.0456x; 1.0456x over previous
#include <cuda_runtime.h>
#include <cuda_bf16.h>
#include <math.h>
#include <stdint.h>

#define NN 10000
#define KK 16
#define EE (NN*KK)
#define HH 100
#define NB 10
#define NBP 16

// ---------------- scratch ----------------
__device__ float g_basis[EE*NBP];
__device__ float g_u[EE*3];
__device__ float g_h1[EE*HH];
__device__ float g_h2[EE*HH];
__device__ __nv_bfloat16 g_W[(size_t)EE*832];   // bf16 W: 266 MB
__device__ float g_f0a[NN*32];
__device__ float g_f0b[NN*32];
__device__ float g_f1a[NN*24];
__device__ float g_f1b[NN*24];
__device__ float g_w1t[NBP*HH];
__device__ float g_w2t[HH*HH];
__device__ float g_w3t[HH*832];

// ---------------- helpers ----------------
__device__ __forceinline__ float f2tf32f(float v) {
    uint32_t r;
    asm("cvt.rna.tf32.f32 %0, %1;" : "=r"(r) : "f"(v));
    return __uint_as_float(r);
}

__device__ __forceinline__ void mma_tf32(float* c, const uint32_t* a, const uint32_t* b) {
    asm volatile("mma.sync.aligned.m16n8k8.row.col.f32.tf32.tf32.f32 "
        "{%0,%1,%2,%3}, {%4,%5,%6,%7}, {%8,%9}, {%0,%1,%2,%3};"
        : "+f"(c[0]), "+f"(c[1]), "+f"(c[2]), "+f"(c[3])
        : "r"(a[0]), "r"(a[1]), "r"(a[2]), "r"(a[3]), "r"(b[0]), "r"(b[1]));
}

__device__ __forceinline__ void cp16(void* dst_smem, const void* src, int bytes) {
    uint32_t d = (uint32_t)__cvta_generic_to_shared(dst_smem);
    asm volatile("cp.async.cg.shared.global [%0], [%1], 16, %2;"
                 :: "r"(d), "l"(src), "r"(bytes));
}

// ---------------- prep ----------------
__global__ void prep_kernel(const float* __restrict__ radii) {
    int e = blockIdx.x*blockDim.x + threadIdx.x;
    if (e >= EE) return;
    float x = radii[e*3+0], y = radii[e*3+1], z = radii[e*3+2];
    float r = sqrtf(x*x + y*y + z*z);
    float inv = 1.0f / (r + 1e-8f);
    g_u[e*3+0] = x*inv; g_u[e*3+1] = y*inv; g_u[e*3+2] = z*inv;
    float rs = r * 1.8f;
    #pragma unroll
    for (int b = 0; b < NBP; b++) {
        float v = 0.f;
        if (b < NB) {
            float d = rs - (float)b;
            if (fabsf(d) < 1.0f) {
                float c = cospif(0.5f * d);
                v = f2tf32f(c * c);
            }
        }
        g_basis[e*NBP + b] = v;
    }
}

// ---------------- weight pre-round ----------------
__global__ void cvt_kernel(const float* __restrict__ src, float* __restrict__ dst, int n) {
    int i = blockIdx.x*blockDim.x + threadIdx.x;
    if (i < n) dst[i] = f2tf32f(src[i]);
}
__global__ void cvt_pad_kernel(const float* __restrict__ src, float* __restrict__ dst) {
    int i = blockIdx.x*blockDim.x + threadIdx.x;
    if (i >= NBP*HH) return;
    int row = i / HH;
    dst[i] = (row < NB) ? f2tf32f(src[i]) : 0.f;
}

// ---------------- tf32 tensor-core GEMM, cp.async double-buffered ----------------
// C[M,N] = act(A[M,K] @ B[K,N] + bias). BM=128, BN=128, BK=32, 256 thr.
// OUT: 0 = fp32, 1 = fp32 tf32-rounded, 2 = bf16.
#define AS_STRIDE 36
#define BS_STRIDE 136
#define AS_BUF (128*AS_STRIDE)
#define BS_BUF (32*BS_STRIDE)
#define SMEM_FLOATS (2*AS_BUF + 2*BS_BUF)

template<bool RELU, int OUT>
__global__ void __launch_bounds__(256, 2)
gemm_tc(const float* __restrict__ A, const float* __restrict__ B,
        const float* __restrict__ bias, void* __restrict__ Cp,
        int M, int N, int K) {
    extern __shared__ float smem[];
    float* As = smem;
    float* Bs = smem + 2*AS_BUF;

    const int tid = threadIdx.x;
    const int lane = tid & 31, wid = tid >> 5;
    const int wm = (wid & 1) * 64;
    const int wn = (wid >> 1) * 32;
    const int m0 = blockIdx.y * 128, n0 = blockIdx.x * 128;
    const int gr = lane >> 2, tg = lane & 3;

    float acc[4][4][4] = {};
    const int ntiles = (K + 31) >> 5;

    auto load_tile = [&](int t, int buf) {
        int kc = t << 5;
        float* Ad = As + buf*AS_BUF;
        #pragma unroll
        for (int j = 0; j < 4; j++) {
            int c = tid + j*256;
            int row = c >> 3, kch = (c & 7) * 4;
            int gk = kc + kch;
            int bytes = (K - gk) * 4;
            bytes = bytes < 0 ? 0 : (bytes > 16 ? 16 : bytes);
            const float* src = bytes ? (A + (size_t)(m0+row)*K + gk) : A;
            cp16(Ad + row*AS_STRIDE + kch, src, bytes);
        }
        float* Bd = Bs + buf*BS_BUF;
        #pragma unroll
        for (int j = 0; j < 4; j++) {
            int c = tid + j*256;
            int k = c >> 5, nch = (c & 31) * 4;
            int gk = kc + k;
            int bytes = 0;
            if (gk < K) {
                bytes = (N - (n0 + nch)) * 4;
                bytes = bytes < 0 ? 0 : (bytes > 16 ? 16 : bytes);
            }
            const float* src = bytes ? (B + (size_t)gk*N + n0 + nch) : B;
            cp16(Bd + k*BS_STRIDE + nch, src, bytes);
        }
        asm volatile("cp.async.commit_group;");
    };

    load_tile(0, 0);

    for (int t = 0; t < ntiles; t++) {
        if (t + 1 < ntiles) {
            load_tile(t + 1, (t + 1) & 1);
            asm volatile("cp.async.wait_group 1;");
        } else {
            asm volatile("cp.async.wait_group 0;");
        }
        __syncthreads();
        const float* Ab = As + (t & 1)*AS_BUF;
        const float* Bb = Bs + (t & 1)*BS_BUF;
        #pragma unroll
        for (int k8 = 0; k8 < 4; k8++) {
            int k0 = k8 * 8;
            uint32_t a[4][4], b[4][2];
            #pragma unroll
            for (int t2 = 0; t2 < 4; t2++) {
                int row = wm + t2*16 + gr;
                a[t2][0] = __float_as_uint(Ab[row*AS_STRIDE     + k0 + tg]);
                a[t2][1] = __float_as_uint(Ab[(row+8)*AS_STRIDE + k0 + tg]);
                a[t2][2] = __float_as_uint(Ab[row*AS_STRIDE     + k0 + 4 + tg]);
                a[t2][3] = __float_as_uint(Ab[(row+8)*AS_STRIDE + k0 + 4 + tg]);
            }
            #pragma unroll
            for (int j = 0; j < 4; j++) {
                int col = wn + j*8 + gr;
                b[j][0] = __float_as_uint(Bb[(k0 + tg)*BS_STRIDE     + col]);
                b[j][1] = __float_as_uint(Bb[(k0 + 4 + tg)*BS_STRIDE + col]);
            }
            #pragma unroll
            for (int t2 = 0; t2 < 4; t2++)
                #pragma unroll
                for (int j = 0; j < 4; j++)
                    mma_tf32(acc[t2][j], a[t2], b[j]);
        }
        __syncthreads();
    }

    float* Cf = (float*)Cp;
    __nv_bfloat16* Cb = (__nv_bfloat16*)Cp;

    #pragma unroll
    for (int t2 = 0; t2 < 4; t2++) {
        #pragma unroll
        for (int j = 0; j < 4; j++) {
            int row = m0 + wm + t2*16 + gr;
            int col = n0 + wn + j*8 + tg*2;
            #pragma unroll
            for (int h = 0; h < 2; h++) {
                int r = row + h*8;
                #pragma unroll
                for (int q = 0; q < 2; q++) {
                    int cn = col + q;
                    if (cn < N) {
                        float v = acc[t2][j][h*2 + q];
                        if (bias) v += bias[cn];
                        if (RELU) v = fmaxf(v, 0.f);
                        if (OUT == 1) {
                            Cf[(size_t)r*N + cn] = f2tf32f(v);
                        } else if (OUT == 2) {
                            Cb[(size_t)r*N + cn] = __float2bfloat16(v);
                        } else {
                            Cf[(size_t)r*N + cn] = v;
                        }
                    }
                }
            }
        }
    }
}

// ---------------- tensor product + mean-over-K + gated nonlinearity (bf16 W) ----------------
template<int LAYER>
__global__ void tp_kernel(const int* __restrict__ nbr, const int* __restrict__ charges) {
    constexpr int M0I = (LAYER==1) ? 1 : 16;
    constexpr int M1I = (LAYER==1) ? 0 : 8;
    constexpr int M0O = (LAYER==3) ? 32 : 16;
    constexpr int NG  = (LAYER==3) ? 0 : 8;
    constexpr int M1O = (LAYER==3) ? 0 : 8;
    constexpr int M0T = M0O + NG;
    constexpr int OFF1 = M0T*M0I;
    constexpr int OFF2 = OFF1 + M0T*M1I;
    constexpr int OFF3 = OFF2 + M1O*M0I;
    constexpr int OFF4 = OFF3 + M1O*M1I;
    constexpr int WTOT = OFF4 + M1O*M1I;

    const float* __restrict__ f0_in = (LAYER==2) ? g_f0a : g_f0b;
    const float* __restrict__ f1_in = (LAYER==2) ? g_f1a : g_f1b;
    float* f0_out = (LAYER==2) ? g_f0b : g_f0a;
    float* f1_out = (LAYER==2) ? g_f1b : g_f1a;

    int n = blockIdx.x;
    int tid = threadIdx.x;

    __shared__ float g0s[16], us[3], g1s[24], ps[8], gates[8];

    float acc = 0.f;

    for (int k = 0; k < KK; k++) {
        int e = n*KK + k;
        int idx = nbr[e];
        if (LAYER == 1) {
            if (tid == 0) g0s[0] = 0.5f * ((float)charges[idx] / 94.0f - 0.5f);
        } else {
            if (tid < M0I) g0s[tid] = 0.5f * f0_in[idx*M0I + tid];
        }
        if (tid >= 32 && tid < 35) us[tid-32] = g_u[e*3 + (tid-32)];
        if (M1I > 0) {
            if (tid >= 36 && tid < 36 + M1I*3) g1s[tid-36] = 0.5f * f1_in[idx*(M1I*3) + (tid-36)];
        }
        __syncthreads();
        if (M1I > 0) {
            if (tid < M1I) ps[tid] = g1s[tid*3]*us[0] + g1s[tid*3+1]*us[1] + g1s[tid*3+2]*us[2];
        }
        __syncthreads();
        const __nv_bfloat16* __restrict__ We = g_W + (size_t)e * WTOT;
        if (tid < M0T) {
            float s = 0.f;
            #pragma unroll
            for (int i = 0; i < M0I; i++) s += __bfloat162float(We[tid*M0I + i]) * g0s[i];
            if (M1I > 0) {
                #pragma unroll
                for (int i = 0; i < M1I; i++) s += __bfloat162float(We[OFF1 + tid*M1I + i]) * ps[i];
            }
            acc += s;
        } else if (M1O > 0 && tid < M0T + 3*M1O) {
            int q = tid - M0T, o = q/3, c = q - o*3;
            float dot = 0.f;
            #pragma unroll
            for (int i = 0; i < M0I; i++) dot += __bfloat162float(We[OFF2 + o*M0I + i]) * g0s[i];
            float vv = dot * us[c];
            if (M1I > 0) {
                int c1 = (c+1)%3, c2 = (c+2)%3;
                #pragma unroll
                for (int i = 0; i < M1I; i++) vv += __bfloat162float(We[OFF3 + o*M1I + i]) * g1s[i*3 + c];
                #pragma unroll
                for (int i = 0; i < M1I; i++)
                    vv += __bfloat162float(We[OFF4 + o*M1I + i]) * (g1s[i*3+c1]*us[c2] - g1s[i*3+c2]*us[c1]);
            }
            acc += vv;
        }
        __syncthreads();
    }

    float m = acc * (1.0f/16.0f);
    if (tid < M0O) {
        f0_out[n*M0O + tid] = fmaxf(m, 0.f);
    } else if (tid < M0T) {
        gates[tid - M0O] = 1.0f / (1.0f + expf(-m));
    }
    __syncthreads();
    if (M1O > 0 && tid >= M0T && tid < M0T + 3*M1O) {
        int q = tid - M0T, o = q/3, c = q - o*3;
        f1_out[(n*M1O + o)*3 + c] = m * gates[o];
    }
}

// ---------------- final reduce ----------------
__global__ void reduce_kernel(float* __restrict__ out) {
    __shared__ float red[256];
    int j = blockIdx.x;
    float s = 0.f;
    for (int n = threadIdx.x; n < NN; n += 256) s += g_f0a[n*32 + j];
    red[threadIdx.x] = s;
    __syncthreads();
    for (int w = 128; w > 0; w >>= 1) {
        if (threadIdx.x < w) red[threadIdx.x] += red[threadIdx.x + w];
        __syncthreads();
    }
    if (threadIdx.x == 0) out[j] = red[0] * (1.0f/NN);
}

// ---------------- host ----------------
extern "C" void kernel_launch(void* const* d_in, const int* in_sizes, int n_in,
                              void* d_out, int out_size) {
    const float* radii   = (const float*)d_in[0];
    const int*   nbr     = (const int*)d_in[1];
    const int*   charges = (const int*)d_in[2];

    void* p;
    cudaGetSymbolAddress(&p, g_basis); float* basis = (float*)p;
    cudaGetSymbolAddress(&p, g_h1);    float* h1    = (float*)p;
    cudaGetSymbolAddress(&p, g_h2);    float* h2    = (float*)p;
    cudaGetSymbolAddress(&p, g_W);     void*  W     = p;
    cudaGetSymbolAddress(&p, g_w1t);   float* w1t   = (float*)p;
    cudaGetSymbolAddress(&p, g_w2t);   float* w2t   = (float*)p;
    cudaGetSymbolAddress(&p, g_w3t);   float* w3t   = (float*)p;

    const int smem_bytes = SMEM_FLOATS * 4;   // 71680
    cudaFuncSetAttribute(gemm_tc<true , 1>, cudaFuncAttributeMaxDynamicSharedMemorySize, smem_bytes);
    cudaFuncSetAttribute(gemm_tc<false, 2>, cudaFuncAttributeMaxDynamicSharedMemorySize, smem_bytes);

    prep_kernel<<<(EE+255)/256, 256>>>(radii);

    const int wtot[3] = {32, 832, 768};
    for (int l = 0; l < 3; l++) {
        const float* w1 = (const float*)d_in[3 + 5*l + 0];
        const float* b1 = (const float*)d_in[3 + 5*l + 1];
        const float* w2 = (const float*)d_in[3 + 5*l + 2];
        const float* b2 = (const float*)d_in[3 + 5*l + 3];
        const float* w3 = (const float*)d_in[3 + 5*l + 4];

        cvt_pad_kernel<<<(NBP*HH+255)/256, 256>>>(w1, w1t);
        cvt_kernel<<<(HH*HH+255)/256, 256>>>(w2, w2t, HH*HH);
        cvt_kernel<<<(HH*wtot[l]+255)/256, 256>>>(w3, w3t, HH*wtot[l]);

        dim3 gridH(1, EE/128);                     // N=100 fits one 128-col tile
        gemm_tc<true , 1><<<gridH, 256, smem_bytes>>>(basis, w1t, b1, h1, EE, HH, NBP);
        gemm_tc<true , 1><<<gridH, 256, smem_bytes>>>(h1,    w2t, b2, h2, EE, HH, HH);
        dim3 gridW((wtot[l] + 127)/128, EE/128);
        gemm_tc<false, 2><<<gridW, 256, smem_bytes>>>(h2,    w3t, nullptr, W, EE, wtot[l], HH);

        if      (l == 0) tp_kernel<1><<<NN, 64>>>(nbr, charges);
        else if (l == 1) tp_kernel<2><<<NN, 64>>>(nbr, charges);
        else             tp_kernel<3><<<NN, 64>>>(nbr, charges);
    }
    reduce_kernel<<<32, 256>>>((float*)d_out);
}

// round 9
// speedup vs baseline: 1.0647x; 1.0182x over previous
#include <cuda_runtime.h>
#include <math.h>
#include <stdint.h>

#define NN 10000
#define KK 16
#define EE (NN*KK)
#define HH 100
#define NB 10
#define NBP 16

// ---------------- scratch ----------------
__device__ float g_basis[EE*NBP];
__device__ float g_u[EE*3];
__device__ float g_h1[EE*HH];
__device__ float g_h2[EE*HH];
__device__ float g_f0a[NN*32];
__device__ float g_f0b[NN*32];
__device__ float g_f1a[NN*24];
__device__ float g_f1b[NN*24];
__device__ float g_w1t[NBP*HH];
__device__ float g_w2t[HH*HH];
__device__ float g_w3r[HH*832];

// ---------------- helpers ----------------
__device__ __forceinline__ float f2tf32f(float v) {
    uint32_t r;
    asm("cvt.rna.tf32.f32 %0, %1;" : "=r"(r) : "f"(v));
    return __uint_as_float(r);
}

__device__ __forceinline__ void mma_tf32(float* c, const uint32_t* a, const uint32_t* b) {
    asm volatile("mma.sync.aligned.m16n8k8.row.col.f32.tf32.tf32.f32 "
        "{%0,%1,%2,%3}, {%4,%5,%6,%7}, {%8,%9}, {%0,%1,%2,%3};"
        : "+f"(c[0]), "+f"(c[1]), "+f"(c[2]), "+f"(c[3])
        : "r"(a[0]), "r"(a[1]), "r"(a[2]), "r"(a[3]), "r"(b[0]), "r"(b[1]));
}

__device__ __forceinline__ void cp16(void* dst_smem, const void* src, int bytes) {
    uint32_t d = (uint32_t)__cvta_generic_to_shared(dst_smem);
    asm volatile("cp.async.cg.shared.global [%0], [%1], 16, %2;"
                 :: "r"(d), "l"(src), "r"(bytes));
}

// ---------------- prep ----------------
__global__ void prep_kernel(const float* __restrict__ radii) {
    int e = blockIdx.x*blockDim.x + threadIdx.x;
    if (e >= EE) return;
    float x = radii[e*3+0], y = radii[e*3+1], z = radii[e*3+2];
    float r = sqrtf(x*x + y*y + z*z);
    float inv = 1.0f / (r + 1e-8f);
    g_u[e*3+0] = x*inv; g_u[e*3+1] = y*inv; g_u[e*3+2] = z*inv;
    float rs = r * 1.8f;
    #pragma unroll
    for (int b = 0; b < NBP; b++) {
        float v = 0.f;
        if (b < NB) {
            float d = rs - (float)b;
            if (fabsf(d) < 1.0f) {
                float c = cospif(0.5f * d);
                v = f2tf32f(c * c);
            }
        }
        g_basis[e*NBP + b] = v;
    }
}

// ---------------- weight pre-round (radial MLP only) ----------------
__global__ void cvt_kernel(const float* __restrict__ src, float* __restrict__ dst, int n) {
    int i = blockIdx.x*blockDim.x + threadIdx.x;
    if (i < n) dst[i] = f2tf32f(src[i]);
}
__global__ void cvt_pad_kernel(const float* __restrict__ src, float* __restrict__ dst) {
    int i = blockIdx.x*blockDim.x + threadIdx.x;
    if (i >= NBP*HH) return;
    int row = i / HH;
    dst[i] = (row < NB) ? f2tf32f(src[i]) : 0.f;
}

// ---------------- w3 rearrange: [k][o][i] -> [k][i][o] per block (fp32 exact) ----------------
template<int LAYER>
__global__ void rearr_kernel(const float* __restrict__ w3, float* __restrict__ w3r) {
    constexpr int WTOT = (LAYER==1) ? 32 : (LAYER==2) ? 832 : 768;
    int idx = blockIdx.x*blockDim.x + threadIdx.x;
    if (idx >= HH*WTOT) return;
    int k = idx / WTOT, d = idx - k*WTOT;
    int src;
    if (LAYER == 1) {
        src = d;                                        // identity (m0i=1)
    } else if (LAYER == 2) {
        if      (d < 384) { int o=d%24,      i=d/24;       src = o*16 + i; }
        else if (d < 576) { int t=d-384; int o=t%24, i=t/24; src = 384 + o*8 + i; }
        else if (d < 704) { int t=d-576; int o=t%8,  i=t/8;  src = 576 + o*16 + i; }
        else if (d < 768) { int t=d-704; int o=t%8,  i=t/8;  src = 704 + o*8 + i; }
        else              { int t=d-768; int o=t%8,  i=t/8;  src = 768 + o*8 + i; }
    } else {
        if (d < 512) { int o=d%32, i=d/32; src = o*16 + i; }
        else         { int t=d-512; int o=t%32, i=t/32; src = 512 + o*8 + i; }
    }
    w3r[k*WTOT + d] = w3[k*WTOT + src];
}

// ---------------- tf32 tensor-core GEMM (R6-verified), OUT: 0=fp32, 1=tf32-rounded ----------------
#define AS_STRIDE 36
#define BS_STRIDE 136
#define AS_BUF (128*AS_STRIDE)
#define BS_BUF (32*BS_STRIDE)
#define SMEM_FLOATS (2*AS_BUF + 2*BS_BUF)

template<bool RELU, int OUT>
__global__ void __launch_bounds__(256, 2)
gemm_tc(const float* __restrict__ A, const float* __restrict__ B,
        const float* __restrict__ bias, float* __restrict__ C,
        int M, int N, int K) {
    extern __shared__ float smem[];
    float* As = smem;
    float* Bs = smem + 2*AS_BUF;

    const int tid = threadIdx.x;
    const int lane = tid & 31, wid = tid >> 5;
    const int wm = (wid & 1) * 64;
    const int wn = (wid >> 1) * 32;
    const int m0 = blockIdx.y * 128, n0 = blockIdx.x * 128;
    const int gr = lane >> 2, tg = lane & 3;

    float acc[4][4][4] = {};
    const int ntiles = (K + 31) >> 5;

    auto load_tile = [&](int t, int buf) {
        int kc = t << 5;
        float* Ad = As + buf*AS_BUF;
        #pragma unroll
        for (int j = 0; j < 4; j++) {
            int c = tid + j*256;
            int row = c >> 3, kch = (c & 7) * 4;
            int gk = kc + kch;
            int bytes = (K - gk) * 4;
            bytes = bytes < 0 ? 0 : (bytes > 16 ? 16 : bytes);
            const float* src = bytes ? (A + (size_t)(m0+row)*K + gk) : A;
            cp16(Ad + row*AS_STRIDE + kch, src, bytes);
        }
        float* Bd = Bs + buf*BS_BUF;
        #pragma unroll
        for (int j = 0; j < 4; j++) {
            int c = tid + j*256;
            int k = c >> 5, nch = (c & 31) * 4;
            int gk = kc + k;
            int bytes = 0;
            if (gk < K) {
                bytes = (N - (n0 + nch)) * 4;
                bytes = bytes < 0 ? 0 : (bytes > 16 ? 16 : bytes);
            }
            const float* src = bytes ? (B + (size_t)gk*N + n0 + nch) : B;
            cp16(Bd + k*BS_STRIDE + nch, src, bytes);
        }
        asm volatile("cp.async.commit_group;");
    };

    load_tile(0, 0);

    for (int t = 0; t < ntiles; t++) {
        if (t + 1 < ntiles) {
            load_tile(t + 1, (t + 1) & 1);
            asm volatile("cp.async.wait_group 1;");
        } else {
            asm volatile("cp.async.wait_group 0;");
        }
        __syncthreads();
        const float* Ab = As + (t & 1)*AS_BUF;
        const float* Bb = Bs + (t & 1)*BS_BUF;
        #pragma unroll
        for (int k8 = 0; k8 < 4; k8++) {
            int k0 = k8 * 8;
            uint32_t a[4][4], b[4][2];
            #pragma unroll
            for (int t2 = 0; t2 < 4; t2++) {
                int row = wm + t2*16 + gr;
                a[t2][0] = __float_as_uint(Ab[row*AS_STRIDE     + k0 + tg]);
                a[t2][1] = __float_as_uint(Ab[(row+8)*AS_STRIDE + k0 + tg]);
                a[t2][2] = __float_as_uint(Ab[row*AS_STRIDE     + k0 + 4 + tg]);
                a[t2][3] = __float_as_uint(Ab[(row+8)*AS_STRIDE + k0 + 4 + tg]);
            }
            #pragma unroll
            for (int j = 0; j < 4; j++) {
                int col = wn + j*8 + gr;
                b[j][0] = __float_as_uint(Bb[(k0 + tg)*BS_STRIDE     + col]);
                b[j][1] = __float_as_uint(Bb[(k0 + 4 + tg)*BS_STRIDE + col]);
            }
            #pragma unroll
            for (int t2 = 0; t2 < 4; t2++)
                #pragma unroll
                for (int j = 0; j < 4; j++)
                    mma_tf32(acc[t2][j], a[t2], b[j]);
        }
        __syncthreads();
    }

    #pragma unroll
    for (int t2 = 0; t2 < 4; t2++) {
        #pragma unroll
        for (int j = 0; j < 4; j++) {
            int row = m0 + wm + t2*16 + gr;
            int col = n0 + wn + j*8 + tg*2;
            #pragma unroll
            for (int h = 0; h < 2; h++) {
                int r = row + h*8;
                #pragma unroll
                for (int q = 0; q < 2; q++) {
                    int cn = col + q;
                    if (cn < N) {
                        float v = acc[t2][j][h*2 + q];
                        if (bias) v += bias[cn];
                        if (RELU) v = fmaxf(v, 0.f);
                        if (OUT == 1) v = f2tf32f(v);
                        C[(size_t)r*N + cn] = v;
                    }
                }
            }
        }
    }
}

// ---------------- fused node kernel: M-build + w3 contraction + mean + gating ----------------
// One CTA = one node (16 edges). M[k,f] = sum_e h2[e,k] z[e,f] in smem (100 x F),
// then out[slot] = sum_{k,i} w3r[k,i,o] * M[k,f(i,c)]. W never materialized.
template<int LAYER>
__global__ void __launch_bounds__(256)
node_tp(const int* __restrict__ nbr, const int* __restrict__ charges,
        const float* __restrict__ h2, const float* __restrict__ w3r) {
    constexpr int F     = (LAYER==1) ? 4   : (LAYER==2) ? 120 : 24;
    constexpr int WTOT  = (LAYER==1) ? 32  : (LAYER==2) ? 832 : 768;
    constexpr int NSLOT = (LAYER==3) ? 32  : 48;     // 24 scalar (+8 gate) + 8x3 vector
    constexpr int KG    = (LAYER==3) ? 8   : 5;

    extern __shared__ float sm[];
    float* h2s  = sm;                    // 16*100
    float* zs   = h2s + 16*100;          // 16*F
    float* Ms   = zs + 16*F;             // 100*F
    float* part = Ms + 100*F;            // KG*NSLOT
    float* gsm  = part + KG*NSLOT;       // 8

    const int tid = threadIdx.x;
    const int n = blockIdx.x;

    const float* __restrict__ f0in = (LAYER==2) ? g_f0a : g_f0b;
    const float* __restrict__ f1in = (LAYER==2) ? g_f1a : g_f1b;
    float* f0out = (LAYER==2) ? g_f0b : g_f0a;
    float* f1out = (LAYER==2) ? g_f1b : g_f1a;

    // ---- Phase A: build z features (16 threads per edge) ----
    {
        int e = tid >> 4, j = tid & 15;
        int ge = n*KK + e;
        int idx = nbr[ge];
        float u0 = g_u[ge*3+0], u1 = g_u[ge*3+1], u2 = g_u[ge*3+2];
        if (LAYER == 1) {
            if (j == 0) {
                float g0 = 0.5f * ((float)charges[idx] / 94.0f - 0.5f);
                zs[e*F+0] = g0;
                zs[e*F+1] = g0*u0; zs[e*F+2] = g0*u1; zs[e*F+3] = g0*u2;
            }
        } else {
            float g0j = 0.5f * f0in[idx*16 + j];
            zs[e*F + j] = g0j;
            if (LAYER == 2) {
                zs[e*F + 24 + j*3 + 0] = g0j*u0;
                zs[e*F + 24 + j*3 + 1] = g0j*u1;
                zs[e*F + 24 + j*3 + 2] = g0j*u2;
            }
            if (j < 8) {
                float a = 0.5f * f1in[idx*24 + j*3 + 0];
                float b = 0.5f * f1in[idx*24 + j*3 + 1];
                float c = 0.5f * f1in[idx*24 + j*3 + 2];
                zs[e*F + 16 + j] = a*u0 + b*u1 + c*u2;      // p = g1 . u
                if (LAYER == 2) {
                    zs[e*F + 72 + j*3 + 0] = a;
                    zs[e*F + 72 + j*3 + 1] = b;
                    zs[e*F + 72 + j*3 + 2] = c;
                    zs[e*F + 96 + j*3 + 0] = b*u2 - c*u1;   // cross(g1,u)
                    zs[e*F + 96 + j*3 + 1] = c*u0 - a*u2;
                    zs[e*F + 96 + j*3 + 2] = a*u1 - b*u0;
                }
            }
        }
    }

    // ---- Phase B: stage h2 tile (16 rows x 100, contiguous) ----
    for (int i = tid; i < 16*HH; i += 256)
        h2s[i] = h2[(size_t)n*KK*HH + i];
    __syncthreads();

    // ---- Phase C: M[k,f] = sum_e h2[e,k] * z[e,f] ----
    for (int idx = tid; idx < HH*F; idx += 256) {
        int k = idx / F, f = idx - k*F;
        float m = 0.f;
        #pragma unroll
        for (int e = 0; e < 16; e++)
            m += h2s[e*HH + k] * zs[e*F + f];
        Ms[idx] = m;
    }
    __syncthreads();

    // ---- Phase D: contraction with rearranged w3 ----
    if (tid < KG*NSLOT) {
        int s = tid % NSLOT, g = tid / NSLOT;
        float acc = 0.f;
        for (int k = g; k < HH; k += KG) {
            const float* wr = w3r + k*WTOT;
            const float* Mk = Ms + k*F;
            if (LAYER == 1) {
                if (s < 24) {
                    acc += wr[s] * Mk[0];
                } else {
                    int q = s - 24, o = q/3, c = q - o*3;
                    acc += wr[24 + o] * Mk[1 + c];
                }
            } else if (LAYER == 2) {
                if (s < 24) {
                    #pragma unroll
                    for (int i = 0; i < 16; i++) acc += wr[i*24 + s] * Mk[i];
                    #pragma unroll
                    for (int i = 0; i < 8; i++)  acc += wr[384 + i*24 + s] * Mk[16 + i];
                } else {
                    int q = s - 24, o = q/3, c = q - o*3;
                    #pragma unroll
                    for (int i = 0; i < 16; i++) acc += wr[576 + i*8 + o] * Mk[24 + i*3 + c];
                    #pragma unroll
                    for (int i = 0; i < 8; i++)  acc += wr[704 + i*8 + o] * Mk[72 + i*3 + c];
                    #pragma unroll
                    for (int i = 0; i < 8; i++)  acc += wr[768 + i*8 + o] * Mk[96 + i*3 + c];
                }
            } else {
                #pragma unroll
                for (int i = 0; i < 16; i++) acc += wr[i*32 + s] * Mk[i];
                #pragma unroll
                for (int i = 0; i < 8; i++)  acc += wr[512 + i*32 + s] * Mk[16 + i];
            }
        }
        part[tid] = acc;
    }
    __syncthreads();

    // ---- Phase E: reduce k-groups, mean, nonlinearity ----
    if (tid < NSLOT) {
        float m = 0.f;
        #pragma unroll
        for (int g = 0; g < KG; g++) m += part[g*NSLOT + tid];
        m *= (1.0f/16.0f);
        if (LAYER == 3) {
            f0out[n*32 + tid] = fmaxf(m, 0.f);
        } else {
            part[tid] = m;                         // stage (safe: writer==only same-idx reader)
            if (tid >= 16 && tid < 24)
                gsm[tid - 16] = 1.0f / (1.0f + expf(-m));
        }
    }
    if (LAYER != 3) {
        __syncthreads();
        if (tid < 16) {
            f0out[n*16 + tid] = fmaxf(part[tid], 0.f);
        } else if (tid >= 24 && tid < 48) {
            int q = tid - 24, o = q/3, c = q - o*3;
            f1out[(n*8 + o)*3 + c] = part[tid] * gsm[o];
        }
    }
}

// ---------------- final reduce ----------------
__global__ void reduce_kernel(float* __restrict__ out) {
    __shared__ float red[256];
    int j = blockIdx.x;
    float s = 0.f;
    for (int n = threadIdx.x; n < NN; n += 256) s += g_f0a[n*32 + j];
    red[threadIdx.x] = s;
    __syncthreads();
    for (int w = 128; w > 0; w >>= 1) {
        if (threadIdx.x < w) red[threadIdx.x] += red[threadIdx.x + w];
        __syncthreads();
    }
    if (threadIdx.x == 0) out[j] = red[0] * (1.0f/NN);
}

// ---------------- host ----------------
extern "C" void kernel_launch(void* const* d_in, const int* in_sizes, int n_in,
                              void* d_out, int out_size) {
    const float* radii   = (const float*)d_in[0];
    const int*   nbr     = (const int*)d_in[1];
    const int*   charges = (const int*)d_in[2];

    void* p;
    cudaGetSymbolAddress(&p, g_basis); float* basis = (float*)p;
    cudaGetSymbolAddress(&p, g_h1);    float* h1    = (float*)p;
    cudaGetSymbolAddress(&p, g_h2);    float* h2    = (float*)p;
    cudaGetSymbolAddress(&p, g_w1t);   float* w1t   = (float*)p;
    cudaGetSymbolAddress(&p, g_w2t);   float* w2t   = (float*)p;
    cudaGetSymbolAddress(&p, g_w3r);   float* w3r   = (float*)p;

    const int smem_bytes = SMEM_FLOATS * 4;   // 71680
    cudaFuncSetAttribute(gemm_tc<true, 1>, cudaFuncAttributeMaxDynamicSharedMemorySize, smem_bytes);
    cudaFuncSetAttribute(gemm_tc<true, 0>, cudaFuncAttributeMaxDynamicSharedMemorySize, smem_bytes);

    // node_tp smem sizes
    const int ns1 = (16*100 + 16*4   + 100*4   + 5*48 + 8) * 4;
    const int ns2 = (16*100 + 16*120 + 100*120 + 5*48 + 8) * 4;   // ~63.1 KB
    const int ns3 = (16*100 + 16*24  + 100*24  + 8*32 + 8) * 4;
    cudaFuncSetAttribute(node_tp<1>, cudaFuncAttributeMaxDynamicSharedMemorySize, ns1);
    cudaFuncSetAttribute(node_tp<2>, cudaFuncAttributeMaxDynamicSharedMemorySize, ns2);
    cudaFuncSetAttribute(node_tp<3>, cudaFuncAttributeMaxDynamicSharedMemorySize, ns3);

    prep_kernel<<<(EE+255)/256, 256>>>(radii);

    const int wtot[3] = {32, 832, 768};
    for (int l = 0; l < 3; l++) {
        const float* w1 = (const float*)d_in[3 + 5*l + 0];
        const float* b1 = (const float*)d_in[3 + 5*l + 1];
        const float* w2 = (const float*)d_in[3 + 5*l + 2];
        const float* b2 = (const float*)d_in[3 + 5*l + 3];
        const float* w3 = (const float*)d_in[3 + 5*l + 4];

        cvt_pad_kernel<<<(NBP*HH+255)/256, 256>>>(w1, w1t);
        cvt_kernel<<<(HH*HH+255)/256, 256>>>(w2, w2t, HH*HH);
        int nrw = HH * wtot[l];
        if      (l == 0) rearr_kernel<1><<<(nrw+255)/256, 256>>>(w3, w3r);
        else if (l == 1) rearr_kernel<2><<<(nrw+255)/256, 256>>>(w3, w3r);
        else             rearr_kernel<3><<<(nrw+255)/256, 256>>>(w3, w3r);

        dim3 gridH(1, EE/128);
        gemm_tc<true, 1><<<gridH, 256, smem_bytes>>>(basis, w1t, b1, h1, EE, HH, NBP);
        gemm_tc<true, 0><<<gridH, 256, smem_bytes>>>(h1,    w2t, b2, h2, EE, HH, HH);

        if      (l == 0) node_tp<1><<<NN, 256, ns1>>>(nbr, charges, h2, w3r);
        else if (l == 1) node_tp<2><<<NN, 256, ns2>>>(nbr, charges, h2, w3r);
        else             node_tp<3><<<NN, 256, ns3>>>(nbr, charges, h2, w3r);
    }
    reduce_kernel<<<32, 256>>>((float*)d_out);
}

// round 10
// speedup vs baseline: 1.1578x; 1.0875x over previous
#include <cuda_runtime.h>
#include <math.h>
#include <stdint.h>

#define NN 10000
#define KK 16
#define EE (NN*KK)
#define HH 100
#define NB 10
#define NBP 16

// ---------------- scratch ----------------
__device__ float g_basis[EE*NBP];
__device__ float g_u[EE*3];
__device__ float g_h1[EE*HH];
__device__ float g_h2[EE*HH];
__device__ float g_f0a[NN*32];
__device__ float g_f0b[NN*32];
__device__ float g_f1a[NN*24];
__device__ float g_f1b[NN*24];
__device__ float g_w1t[NBP*HH];
__device__ float g_w2t[HH*HH];
__device__ float g_w3r[HH*832];

// ---------------- helpers ----------------
__device__ __forceinline__ float f2tf32f(float v) {
    uint32_t r;
    asm("cvt.rna.tf32.f32 %0, %1;" : "=r"(r) : "f"(v));
    return __uint_as_float(r);
}

__device__ __forceinline__ void mma_tf32(float* c, const uint32_t* a, const uint32_t* b) {
    asm volatile("mma.sync.aligned.m16n8k8.row.col.f32.tf32.tf32.f32 "
        "{%0,%1,%2,%3}, {%4,%5,%6,%7}, {%8,%9}, {%0,%1,%2,%3};"
        : "+f"(c[0]), "+f"(c[1]), "+f"(c[2]), "+f"(c[3])
        : "r"(a[0]), "r"(a[1]), "r"(a[2]), "r"(a[3]), "r"(b[0]), "r"(b[1]));
}

__device__ __forceinline__ void cp16(void* dst_smem, const void* src, int bytes) {
    uint32_t d = (uint32_t)__cvta_generic_to_shared(dst_smem);
    asm volatile("cp.async.cg.shared.global [%0], [%1], 16, %2;"
                 :: "r"(d), "l"(src), "r"(bytes));
}

// ---------------- prep ----------------
__global__ void prep_kernel(const float* __restrict__ radii) {
    int e = blockIdx.x*blockDim.x + threadIdx.x;
    if (e >= EE) return;
    float x = radii[e*3+0], y = radii[e*3+1], z = radii[e*3+2];
    float r = sqrtf(x*x + y*y + z*z);
    float inv = 1.0f / (r + 1e-8f);
    g_u[e*3+0] = x*inv; g_u[e*3+1] = y*inv; g_u[e*3+2] = z*inv;
    float rs = r * 1.8f;
    #pragma unroll
    for (int b = 0; b < NBP; b++) {
        float v = 0.f;
        if (b < NB) {
            float d = rs - (float)b;
            if (fabsf(d) < 1.0f) {
                float c = cospif(0.5f * d);
                v = f2tf32f(c * c);
            }
        }
        g_basis[e*NBP + b] = v;
    }
}

// ---------------- weight pre-round (radial MLP only) ----------------
__global__ void cvt_kernel(const float* __restrict__ src, float* __restrict__ dst, int n) {
    int i = blockIdx.x*blockDim.x + threadIdx.x;
    if (i < n) dst[i] = f2tf32f(src[i]);
}
__global__ void cvt_pad_kernel(const float* __restrict__ src, float* __restrict__ dst) {
    int i = blockIdx.x*blockDim.x + threadIdx.x;
    if (i >= NBP*HH) return;
    int row = i / HH;
    dst[i] = (row < NB) ? f2tf32f(src[i]) : 0.f;
}

// ---------------- w3 rearrange: [k][o][i] -> [k][i][o] per block (fp32 exact) ----------------
template<int LAYER>
__global__ void rearr_kernel(const float* __restrict__ w3, float* __restrict__ w3r) {
    constexpr int WTOT = (LAYER==1) ? 32 : (LAYER==2) ? 832 : 768;
    int idx = blockIdx.x*blockDim.x + threadIdx.x;
    if (idx >= HH*WTOT) return;
    int k = idx / WTOT, d = idx - k*WTOT;
    int src;
    if (LAYER == 1) {
        src = d;
    } else if (LAYER == 2) {
        if      (d < 384) { int o=d%24,      i=d/24;       src = o*16 + i; }
        else if (d < 576) { int t=d-384; int o=t%24, i=t/24; src = 384 + o*8 + i; }
        else if (d < 704) { int t=d-576; int o=t%8,  i=t/8;  src = 576 + o*16 + i; }
        else if (d < 768) { int t=d-704; int o=t%8,  i=t/8;  src = 704 + o*8 + i; }
        else              { int t=d-768; int o=t%8,  i=t/8;  src = 768 + o*8 + i; }
    } else {
        if (d < 512) { int o=d%32, i=d/32; src = o*16 + i; }
        else         { int t=d-512; int o=t%32, i=t/32; src = 512 + o*8 + i; }
    }
    w3r[k*WTOT + d] = w3[k*WTOT + src];
}

// ---------------- tf32 tensor-core GEMM (R6-verified), OUT: 0=fp32, 1=tf32-rounded ----------------
#define AS_STRIDE 36
#define BS_STRIDE 136
#define AS_BUF (128*AS_STRIDE)
#define BS_BUF (32*BS_STRIDE)
#define SMEM_FLOATS (2*AS_BUF + 2*BS_BUF)

template<bool RELU, int OUT>
__global__ void __launch_bounds__(256, 2)
gemm_tc(const float* __restrict__ A, const float* __restrict__ B,
        const float* __restrict__ bias, float* __restrict__ C,
        int M, int N, int K) {
    extern __shared__ float smem[];
    float* As = smem;
    float* Bs = smem + 2*AS_BUF;

    const int tid = threadIdx.x;
    const int lane = tid & 31, wid = tid >> 5;
    const int wm = (wid & 1) * 64;
    const int wn = (wid >> 1) * 32;
    const int m0 = blockIdx.y * 128, n0 = blockIdx.x * 128;
    const int gr = lane >> 2, tg = lane & 3;

    float acc[4][4][4] = {};
    const int ntiles = (K + 31) >> 5;

    auto load_tile = [&](int t, int buf) {
        int kc = t << 5;
        float* Ad = As + buf*AS_BUF;
        #pragma unroll
        for (int j = 0; j < 4; j++) {
            int c = tid + j*256;
            int row = c >> 3, kch = (c & 7) * 4;
            int gk = kc + kch;
            int bytes = (K - gk) * 4;
            bytes = bytes < 0 ? 0 : (bytes > 16 ? 16 : bytes);
            const float* src = bytes ? (A + (size_t)(m0+row)*K + gk) : A;
            cp16(Ad + row*AS_STRIDE + kch, src, bytes);
        }
        float* Bd = Bs + buf*BS_BUF;
        #pragma unroll
        for (int j = 0; j < 4; j++) {
            int c = tid + j*256;
            int k = c >> 5, nch = (c & 31) * 4;
            int gk = kc + k;
            int bytes = 0;
            if (gk < K) {
                bytes = (N - (n0 + nch)) * 4;
                bytes = bytes < 0 ? 0 : (bytes > 16 ? 16 : bytes);
            }
            const float* src = bytes ? (B + (size_t)gk*N + n0 + nch) : B;
            cp16(Bd + k*BS_STRIDE + nch, src, bytes);
        }
        asm volatile("cp.async.commit_group;");
    };

    load_tile(0, 0);

    for (int t = 0; t < ntiles; t++) {
        if (t + 1 < ntiles) {
            load_tile(t + 1, (t + 1) & 1);
            asm volatile("cp.async.wait_group 1;");
        } else {
            asm volatile("cp.async.wait_group 0;");
        }
        __syncthreads();
        const float* Ab = As + (t & 1)*AS_BUF;
        const float* Bb = Bs + (t & 1)*BS_BUF;
        #pragma unroll
        for (int k8 = 0; k8 < 4; k8++) {
            int k0 = k8 * 8;
            uint32_t a[4][4], b[4][2];
            #pragma unroll
            for (int t2 = 0; t2 < 4; t2++) {
                int row = wm + t2*16 + gr;
                a[t2][0] = __float_as_uint(Ab[row*AS_STRIDE     + k0 + tg]);
                a[t2][1] = __float_as_uint(Ab[(row+8)*AS_STRIDE + k0 + tg]);
                a[t2][2] = __float_as_uint(Ab[row*AS_STRIDE     + k0 + 4 + tg]);
                a[t2][3] = __float_as_uint(Ab[(row+8)*AS_STRIDE + k0 + 4 + tg]);
            }
            #pragma unroll
            for (int j = 0; j < 4; j++) {
                int col = wn + j*8 + gr;
                b[j][0] = __float_as_uint(Bb[(k0 + tg)*BS_STRIDE     + col]);
                b[j][1] = __float_as_uint(Bb[(k0 + 4 + tg)*BS_STRIDE + col]);
            }
            #pragma unroll
            for (int t2 = 0; t2 < 4; t2++)
                #pragma unroll
                for (int j = 0; j < 4; j++)
                    mma_tf32(acc[t2][j], a[t2], b[j]);
        }
        __syncthreads();
    }

    #pragma unroll
    for (int t2 = 0; t2 < 4; t2++) {
        #pragma unroll
        for (int j = 0; j < 4; j++) {
            int row = m0 + wm + t2*16 + gr;
            int col = n0 + wn + j*8 + tg*2;
            #pragma unroll
            for (int h = 0; h < 2; h++) {
                int r = row + h*8;
                #pragma unroll
                for (int q = 0; q < 2; q++) {
                    int cn = col + q;
                    if (cn < N) {
                        float v = acc[t2][j][h*2 + q];
                        if (bias) v += bias[cn];
                        if (RELU) v = fmaxf(v, 0.f);
                        if (OUT == 1) v = f2tf32f(v);
                        C[(size_t)r*N + cn] = v;
                    }
                }
            }
        }
    }
}

// ---------------- multi-node fused TP: M-build + w3 contraction + mean + gating ----------------
// One CTA = NPC nodes. w3 stream amortized across NPC nodes (register reuse in Phase D).
template<int LAYER, int NPC, int THREADS>
__global__ void __launch_bounds__(THREADS)
node_tp(const int* __restrict__ nbr, const int* __restrict__ charges,
        const float* __restrict__ h2, const float* __restrict__ w3r) {
    constexpr int F     = (LAYER==1) ? 4   : (LAYER==2) ? 120 : 24;
    constexpr int WTOT  = (LAYER==1) ? 32  : (LAYER==2) ? 832 : 768;
    constexpr int NSLOT = (LAYER==3) ? 32  : 48;
    constexpr int KG    = (THREADS / NSLOT) > 10 ? 10 : (THREADS / NSLOT);
    constexpr int MF    = HH * F;

    extern __shared__ float sm[];
    float* h2s  = sm;                        // 16*100 (single node staging)
    float* zs   = h2s + 16*HH;               // 16*F (single node staging)
    float* Ms   = zs + 16*F;                 // NPC * 100 * F
    float* part = Ms + NPC*MF;               // KG*NSLOT*NPC
    float* gsm  = part + KG*NSLOT*NPC;       // NPC*8

    const int tid = threadIdx.x;
    const int nbase = blockIdx.x * NPC;

    const float* __restrict__ f0in = (LAYER==2) ? g_f0a : g_f0b;
    const float* __restrict__ f1in = (LAYER==2) ? g_f1a : g_f1b;
    float* f0out = (LAYER==2) ? g_f0b : g_f0a;
    float* f1out = (LAYER==2) ? g_f1b : g_f1a;

    // ---- Phases A/B/C per node ----
    for (int p = 0; p < NPC; p++) {
        int n = nbase + p;
        // Phase A: build z (16 threads per edge; first 256 threads)
        if (tid < 256) {
            int e = tid >> 4, j = tid & 15;
            int ge = n*KK + e;
            int idx = nbr[ge];
            float u0 = g_u[ge*3+0], u1 = g_u[ge*3+1], u2 = g_u[ge*3+2];
            if (LAYER == 1) {
                if (j == 0) {
                    float g0 = 0.5f * ((float)charges[idx] / 94.0f - 0.5f);
                    zs[e*F+0] = g0;
                    zs[e*F+1] = g0*u0; zs[e*F+2] = g0*u1; zs[e*F+3] = g0*u2;
                }
            } else {
                float g0j = 0.5f * f0in[idx*16 + j];
                zs[e*F + j] = g0j;
                if (LAYER == 2) {
                    zs[e*F + 24 + j*3 + 0] = g0j*u0;
                    zs[e*F + 24 + j*3 + 1] = g0j*u1;
                    zs[e*F + 24 + j*3 + 2] = g0j*u2;
                }
                if (j < 8) {
                    float a = 0.5f * f1in[idx*24 + j*3 + 0];
                    float b = 0.5f * f1in[idx*24 + j*3 + 1];
                    float c = 0.5f * f1in[idx*24 + j*3 + 2];
                    zs[e*F + 16 + j] = a*u0 + b*u1 + c*u2;
                    if (LAYER == 2) {
                        zs[e*F + 72 + j*3 + 0] = a;
                        zs[e*F + 72 + j*3 + 1] = b;
                        zs[e*F + 72 + j*3 + 2] = c;
                        zs[e*F + 96 + j*3 + 0] = b*u2 - c*u1;
                        zs[e*F + 96 + j*3 + 1] = c*u0 - a*u2;
                        zs[e*F + 96 + j*3 + 2] = a*u1 - b*u0;
                    }
                }
            }
        }
        // Phase B: stage h2 tile
        for (int i = tid; i < 16*HH; i += THREADS)
            h2s[i] = h2[(size_t)n*KK*HH + i];
        __syncthreads();
        // Phase C: M[k,f]
        float* Mp = Ms + p*MF;
        for (int idx = tid; idx < MF; idx += THREADS) {
            int k = idx / F, f = idx - k*F;
            float m = 0.f;
            #pragma unroll
            for (int e = 0; e < 16; e++)
                m += h2s[e*HH + k] * zs[e*F + f];
            Mp[idx] = m;
        }
        __syncthreads();
    }

    // ---- Phase D: contraction, w3 values reused across NPC nodes ----
    if (tid < KG*NSLOT) {
        int s = tid % NSLOT, g = tid / NSLOT;
        float acc[NPC];
        #pragma unroll
        for (int p = 0; p < NPC; p++) acc[p] = 0.f;

        for (int k = g; k < HH; k += KG) {
            const float* wr = w3r + k*WTOT;
            const float* Mk = Ms + k*F;
            if (LAYER == 1) {
                if (s < 24) {
                    float wv = wr[s];
                    #pragma unroll
                    for (int p = 0; p < NPC; p++) acc[p] += wv * Mk[p*MF + 0];
                } else {
                    int q = s - 24, o = q/3, c = q - o*3;
                    float wv = wr[24 + o];
                    #pragma unroll
                    for (int p = 0; p < NPC; p++) acc[p] += wv * Mk[p*MF + 1 + c];
                }
            } else if (LAYER == 2) {
                if (s < 24) {
                    #pragma unroll
                    for (int i = 0; i < 16; i++) {
                        float wv = wr[i*24 + s];
                        #pragma unroll
                        for (int p = 0; p < NPC; p++) acc[p] += wv * Mk[p*MF + i];
                    }
                    #pragma unroll
                    for (int i = 0; i < 8; i++) {
                        float wv = wr[384 + i*24 + s];
                        #pragma unroll
                        for (int p = 0; p < NPC; p++) acc[p] += wv * Mk[p*MF + 16 + i];
                    }
                } else {
                    int q = s - 24, o = q/3, c = q - o*3;
                    #pragma unroll
                    for (int i = 0; i < 16; i++) {
                        float wv = wr[576 + i*8 + o];
                        #pragma unroll
                        for (int p = 0; p < NPC; p++) acc[p] += wv * Mk[p*MF + 24 + i*3 + c];
                    }
                    #pragma unroll
                    for (int i = 0; i < 8; i++) {
                        float wv = wr[704 + i*8 + o];
                        #pragma unroll
                        for (int p = 0; p < NPC; p++) acc[p] += wv * Mk[p*MF + 72 + i*3 + c];
                    }
                    #pragma unroll
                    for (int i = 0; i < 8; i++) {
                        float wv = wr[768 + i*8 + o];
                        #pragma unroll
                        for (int p = 0; p < NPC; p++) acc[p] += wv * Mk[p*MF + 96 + i*3 + c];
                    }
                }
            } else {
                #pragma unroll
                for (int i = 0; i < 16; i++) {
                    float wv = wr[i*32 + s];
                    #pragma unroll
                    for (int p = 0; p < NPC; p++) acc[p] += wv * Mk[p*MF + i];
                }
                #pragma unroll
                for (int i = 0; i < 8; i++) {
                    float wv = wr[512 + i*32 + s];
                    #pragma unroll
                    for (int p = 0; p < NPC; p++) acc[p] += wv * Mk[p*MF + 16 + i];
                }
            }
        }
        #pragma unroll
        for (int p = 0; p < NPC; p++)
            part[(tid)*NPC + p] = acc[p];
    }
    __syncthreads();

    // ---- Phase E: reduce k-groups, mean, nonlinearity ----
    for (int t2 = tid; t2 < NPC*NSLOT; t2 += THREADS) {
        int p = t2 / NSLOT, s = t2 % NSLOT;
        float m = 0.f;
        #pragma unroll
        for (int g = 0; g < KG; g++) m += part[(g*NSLOT + s)*NPC + p];
        m *= (1.0f/16.0f);
        int n = nbase + p;
        if (LAYER == 3) {
            f0out[n*32 + s] = fmaxf(m, 0.f);
        } else {
            part[s*NPC + p] = m;               // stage (only writer/reader of this column)
            if (s >= 16 && s < 24)
                gsm[p*8 + (s-16)] = 1.0f / (1.0f + expf(-m));
        }
    }
    if (LAYER != 3) {
        __syncthreads();
        for (int t2 = tid; t2 < NPC*NSLOT; t2 += THREADS) {
            int p = t2 / NSLOT, s = t2 % NSLOT;
            int n = nbase + p;
            float m = part[s*NPC + p];
            if (s < 16) {
                f0out[n*16 + s] = fmaxf(m, 0.f);
            } else if (s >= 24) {
                int q = s - 24, o = q/3, c = q - o*3;
                f1out[(n*8 + o)*3 + c] = m * gsm[p*8 + o];
            }
        }
    }
}

// ---------------- final reduce ----------------
__global__ void reduce_kernel(float* __restrict__ out) {
    __shared__ float red[256];
    int j = blockIdx.x;
    float s = 0.f;
    for (int n = threadIdx.x; n < NN; n += 256) s += g_f0a[n*32 + j];
    red[threadIdx.x] = s;
    __syncthreads();
    for (int w = 128; w > 0; w >>= 1) {
        if (threadIdx.x < w) red[threadIdx.x] += red[threadIdx.x + w];
        __syncthreads();
    }
    if (threadIdx.x == 0) out[j] = red[0] * (1.0f/NN);
}

// ---------------- host ----------------
extern "C" void kernel_launch(void* const* d_in, const int* in_sizes, int n_in,
                              void* d_out, int out_size) {
    const float* radii   = (const float*)d_in[0];
    const int*   nbr     = (const int*)d_in[1];
    const int*   charges = (const int*)d_in[2];

    void* p;
    cudaGetSymbolAddress(&p, g_basis); float* basis = (float*)p;
    cudaGetSymbolAddress(&p, g_h1);    float* h1    = (float*)p;
    cudaGetSymbolAddress(&p, g_h2);    float* h2    = (float*)p;
    cudaGetSymbolAddress(&p, g_w1t);   float* w1t   = (float*)p;
    cudaGetSymbolAddress(&p, g_w2t);   float* w2t   = (float*)p;
    cudaGetSymbolAddress(&p, g_w3r);   float* w3r   = (float*)p;

    const int smem_bytes = SMEM_FLOATS * 4;
    cudaFuncSetAttribute(gemm_tc<true, 1>, cudaFuncAttributeMaxDynamicSharedMemorySize, smem_bytes);
    cudaFuncSetAttribute(gemm_tc<true, 0>, cudaFuncAttributeMaxDynamicSharedMemorySize, smem_bytes);

    // node_tp smem sizes (floats): h2s 1600 + zs 16F + Ms NPC*100F + part KG*NSLOT*NPC + gsm 8NPC
    const int ns1 = (1600 + 16*4   + 8*100*4   + 5*48*8  + 64) * 4;   // ~27.4 KB
    const int ns2 = (1600 + 16*120 + 2*100*120 + 10*48*2 + 16) * 4;   // ~114 KB
    const int ns3 = (1600 + 16*24  + 8*100*24  + 8*32*8  + 64) * 4;   // ~93.2 KB
    cudaFuncSetAttribute((const void*)node_tp<1,8,256>, cudaFuncAttributeMaxDynamicSharedMemorySize, ns1);
    cudaFuncSetAttribute((const void*)node_tp<2,2,512>, cudaFuncAttributeMaxDynamicSharedMemorySize, ns2);
    cudaFuncSetAttribute((const void*)node_tp<3,8,256>, cudaFuncAttributeMaxDynamicSharedMemorySize, ns3);

    prep_kernel<<<(EE+255)/256, 256>>>(radii);

    const int wtot[3] = {32, 832, 768};
    for (int l = 0; l < 3; l++) {
        const float* w1 = (const float*)d_in[3 + 5*l + 0];
        const float* b1 = (const float*)d_in[3 + 5*l + 1];
        const float* w2 = (const float*)d_in[3 + 5*l + 2];
        const float* b2 = (const float*)d_in[3 + 5*l + 3];
        const float* w3 = (const float*)d_in[3 + 5*l + 4];

        cvt_pad_kernel<<<(NBP*HH+255)/256, 256>>>(w1, w1t);
        cvt_kernel<<<(HH*HH+255)/256, 256>>>(w2, w2t, HH*HH);
        int nrw = HH * wtot[l];
        if      (l == 0) rearr_kernel<1><<<(nrw+255)/256, 256>>>(w3, w3r);
        else if (l == 1) rearr_kernel<2><<<(nrw+255)/256, 256>>>(w3, w3r);
        else             rearr_kernel<3><<<(nrw+255)/256, 256>>>(w3, w3r);

        dim3 gridH(1, EE/128);
        gemm_tc<true, 1><<<gridH, 256, smem_bytes>>>(basis, w1t, b1, h1, EE, HH, NBP);
        gemm_tc<true, 0><<<gridH, 256, smem_bytes>>>(h1,    w2t, b2, h2, EE, HH, HH);

        if      (l == 0) node_tp<1,8,256><<<NN/8, 256, ns1>>>(nbr, charges, h2, w3r);
        else if (l == 1) node_tp<2,2,512><<<NN/2, 512, ns2>>>(nbr, charges, h2, w3r);
        else             node_tp<3,8,256><<<NN/8, 256, ns3>>>(nbr, charges, h2, w3r);
    }
    reduce_kernel<<<32, 256>>>((float*)d_out);
}

// round 11
// speedup vs baseline: 1.6211x; 1.4002x over previous
#include <cuda_runtime.h>
#include <math.h>
#include <stdint.h>

#define NN 10000
#define KK 16
#define EE (NN*KK)
#define HH 100
#define NB 10
#define NBP 16

// ---------------- scratch ----------------
__device__ float g_basis[EE*NBP];
__device__ float g_u[EE*3];
__device__ float g_h1A[3*EE*HH];
__device__ float g_h2A[3*EE*HH];
__device__ float g_f0a[NN*32];
__device__ float g_f0b[NN*32];
__device__ float g_f1a[NN*24];
__device__ float g_f1b[NN*24];
__device__ float g_w1tA[3*NBP*HH];
__device__ float g_w2tA[3*HH*HH];
__device__ float g_w3rA[3*83200];

struct Bias3 { const float* b[3]; };

// ---------------- helpers ----------------
__device__ __forceinline__ float f2tf32f(float v) {
    uint32_t r;
    asm("cvt.rna.tf32.f32 %0, %1;" : "=r"(r) : "f"(v));
    return __uint_as_float(r);
}

__device__ __forceinline__ void mma_tf32(float* c, const uint32_t* a, const uint32_t* b) {
    asm volatile("mma.sync.aligned.m16n8k8.row.col.f32.tf32.tf32.f32 "
        "{%0,%1,%2,%3}, {%4,%5,%6,%7}, {%8,%9}, {%0,%1,%2,%3};"
        : "+f"(c[0]), "+f"(c[1]), "+f"(c[2]), "+f"(c[3])
        : "r"(a[0]), "r"(a[1]), "r"(a[2]), "r"(a[3]), "r"(b[0]), "r"(b[1]));
}

__device__ __forceinline__ void cp16(void* dst_smem, const void* src, int bytes) {
    uint32_t d = (uint32_t)__cvta_generic_to_shared(dst_smem);
    asm volatile("cp.async.cg.shared.global [%0], [%1], 16, %2;"
                 :: "r"(d), "l"(src), "r"(bytes));
}

// ---------------- prep ----------------
__global__ void prep_kernel(const float* __restrict__ radii) {
    int e = blockIdx.x*blockDim.x + threadIdx.x;
    if (e >= EE) return;
    float x = radii[e*3+0], y = radii[e*3+1], z = radii[e*3+2];
    float r = sqrtf(x*x + y*y + z*z);
    float inv = 1.0f / (r + 1e-8f);
    g_u[e*3+0] = x*inv; g_u[e*3+1] = y*inv; g_u[e*3+2] = z*inv;
    float rs = r * 1.8f;
    #pragma unroll
    for (int b = 0; b < NBP; b++) {
        float v = 0.f;
        if (b < NB) {
            float d = rs - (float)b;
            if (fabsf(d) < 1.0f) {
                float c = cospif(0.5f * d);
                v = f2tf32f(c * c);
            }
        }
        g_basis[e*NBP + b] = v;
    }
}

// ---------------- fused weight prep: all layers, one launch ----------------
// [0,4800): w1t (pad+tf32). [4800,34800): w2t (tf32).
// [34800,198000): w3r (exact fp32 rearrange [k][o][i]->[k][i][o]).
__global__ void prep_weights(
    const float* __restrict__ w1a, const float* __restrict__ w2a, const float* __restrict__ w3a,
    const float* __restrict__ w1b, const float* __restrict__ w2b, const float* __restrict__ w3b,
    const float* __restrict__ w1c, const float* __restrict__ w2c, const float* __restrict__ w3c) {
    int i = blockIdx.x*blockDim.x + threadIdx.x;
    if (i < 4800) {
        int l = i / 1600, r = i - l*1600;
        int row = r / HH;
        const float* s = (l==0) ? w1a : (l==1) ? w1b : w1c;
        g_w1tA[i] = (row < NB) ? f2tf32f(s[r]) : 0.f;
    } else if (i < 34800) {
        int j = i - 4800;
        int l = j / 10000, r = j - l*10000;
        const float* s = (l==0) ? w2a : (l==1) ? w2b : w2c;
        g_w2tA[j] = f2tf32f(s[r]);
    } else {
        int j = i - 34800;
        if (j < 3200) {
            g_w3rA[j] = w3a[j];                           // L1: identity (m0i=1)
        } else if (j < 3200 + 83200) {
            int r = j - 3200;
            int k = r / 832, d = r - k*832;
            int src;
            if      (d < 384) { int o=d%24,      i2=d/24;       src = o*16 + i2; }
            else if (d < 576) { int t=d-384; int o=t%24, i2=t/24; src = 384 + o*8 + i2; }
            else if (d < 704) { int t=d-576; int o=t%8,  i2=t/8;  src = 576 + o*16 + i2; }
            else if (d < 768) { int t=d-704; int o=t%8,  i2=t/8;  src = 704 + o*8 + i2; }
            else              { int t=d-768; int o=t%8,  i2=t/8;  src = 768 + o*8 + i2; }
            g_w3rA[83200 + r] = w3b[k*832 + src];
        } else if (j < 3200 + 83200 + 76800) {
            int r = j - 3200 - 83200;
            int k = r / 768, d = r - k*768;
            int src;
            if (d < 512) { int o=d%32, i2=d/32; src = o*16 + i2; }
            else         { int t=d-512; int o=t%32, i2=t/32; src = 512 + o*8 + i2; }
            g_w3rA[2*83200 + r] = w3c[k*768 + src];
        }
    }
}

// ---------------- tf32 tensor-core GEMM, z-batched over layers ----------------
// C[z][M,N] = act(A[z][M,K] @ B[z][K,N] + bias[z]). BM=128,BN=128,BK=32, 256 thr.
#define AS_STRIDE 36
#define BS_STRIDE 136
#define AS_BUF (128*AS_STRIDE)
#define BS_BUF (32*BS_STRIDE)
#define SMEM_FLOATS (2*AS_BUF + 2*BS_BUF)

template<bool RELU, int OUT>
__global__ void __launch_bounds__(256, 2)
gemm_tc(const float* __restrict__ A0, size_t strideA,
        const float* __restrict__ B0, size_t strideB,
        Bias3 bias3,
        float* __restrict__ C0, size_t strideC,
        int N, int K) {
    extern __shared__ float smem[];
    float* As = smem;
    float* Bs = smem + 2*AS_BUF;

    const float* A = A0 + (size_t)blockIdx.z * strideA;
    const float* B = B0 + (size_t)blockIdx.z * strideB;
    const float* bias = bias3.b[blockIdx.z];
    float* C = C0 + (size_t)blockIdx.z * strideC;

    const int tid = threadIdx.x;
    const int lane = tid & 31, wid = tid >> 5;
    const int wm = (wid & 1) * 64;
    const int wn = (wid >> 1) * 32;
    const int m0 = blockIdx.y * 128, n0 = blockIdx.x * 128;
    const int gr = lane >> 2, tg = lane & 3;

    float acc[4][4][4] = {};
    const int ntiles = (K + 31) >> 5;

    auto load_tile = [&](int t, int buf) {
        int kc = t << 5;
        float* Ad = As + buf*AS_BUF;
        #pragma unroll
        for (int j = 0; j < 4; j++) {
            int c = tid + j*256;
            int row = c >> 3, kch = (c & 7) * 4;
            int gk = kc + kch;
            int bytes = (K - gk) * 4;
            bytes = bytes < 0 ? 0 : (bytes > 16 ? 16 : bytes);
            const float* src = bytes ? (A + (size_t)(m0+row)*K + gk) : A;
            cp16(Ad + row*AS_STRIDE + kch, src, bytes);
        }
        float* Bd = Bs + buf*BS_BUF;
        #pragma unroll
        for (int j = 0; j < 4; j++) {
            int c = tid + j*256;
            int k = c >> 5, nch = (c & 31) * 4;
            int gk = kc + k;
            int bytes = 0;
            if (gk < K) {
                bytes = (N - (n0 + nch)) * 4;
                bytes = bytes < 0 ? 0 : (bytes > 16 ? 16 : bytes);
            }
            const float* src = bytes ? (B + (size_t)gk*N + n0 + nch) : B;
            cp16(Bd + k*BS_STRIDE + nch, src, bytes);
        }
        asm volatile("cp.async.commit_group;");
    };

    load_tile(0, 0);

    for (int t = 0; t < ntiles; t++) {
        if (t + 1 < ntiles) {
            load_tile(t + 1, (t + 1) & 1);
            asm volatile("cp.async.wait_group 1;");
        } else {
            asm volatile("cp.async.wait_group 0;");
        }
        __syncthreads();
        const float* Ab = As + (t & 1)*AS_BUF;
        const float* Bb = Bs + (t & 1)*BS_BUF;
        #pragma unroll
        for (int k8 = 0; k8 < 4; k8++) {
            int k0 = k8 * 8;
            uint32_t a[4][4], b[4][2];
            #pragma unroll
            for (int t2 = 0; t2 < 4; t2++) {
                int row = wm + t2*16 + gr;
                a[t2][0] = __float_as_uint(Ab[row*AS_STRIDE     + k0 + tg]);
                a[t2][1] = __float_as_uint(Ab[(row+8)*AS_STRIDE + k0 + tg]);
                a[t2][2] = __float_as_uint(Ab[row*AS_STRIDE     + k0 + 4 + tg]);
                a[t2][3] = __float_as_uint(Ab[(row+8)*AS_STRIDE + k0 + 4 + tg]);
            }
            #pragma unroll
            for (int j = 0; j < 4; j++) {
                int col = wn + j*8 + gr;
                b[j][0] = __float_as_uint(Bb[(k0 + tg)*BS_STRIDE     + col]);
                b[j][1] = __float_as_uint(Bb[(k0 + 4 + tg)*BS_STRIDE + col]);
            }
            #pragma unroll
            for (int t2 = 0; t2 < 4; t2++)
                #pragma unroll
                for (int j = 0; j < 4; j++)
                    mma_tf32(acc[t2][j], a[t2], b[j]);
        }
        __syncthreads();
    }

    #pragma unroll
    for (int t2 = 0; t2 < 4; t2++) {
        #pragma unroll
        for (int j = 0; j < 4; j++) {
            int row = m0 + wm + t2*16 + gr;
            int col = n0 + wn + j*8 + tg*2;
            #pragma unroll
            for (int h = 0; h < 2; h++) {
                int r = row + h*8;
                #pragma unroll
                for (int q = 0; q < 2; q++) {
                    int cn = col + q;
                    if (cn < N) {
                        float v = acc[t2][j][h*2 + q];
                        v += bias[cn];
                        if (RELU) v = fmaxf(v, 0.f);
                        if (OUT == 1) v = f2tf32f(v);
                        C[(size_t)r*N + cn] = v;
                    }
                }
            }
        }
    }
}

// ---------------- multi-node fused TP (register-tiled, vectorized) ----------------
// z layout: [0..15]=g0, [16..23]=g1.u, then for LAYER==2 c-major vector planes:
//   f = 24 + c*32 + j:  j 0..15 = g0[j]*u[c], 16..23 = g1[j][c], 24..31 = cross(g1,u)[j][c]
template<int LAYER, int NPC, int THREADS>
__global__ void __launch_bounds__(THREADS)
node_tp(const int* __restrict__ nbr, const int* __restrict__ charges,
        const float* __restrict__ h2, const float* __restrict__ w3r) {
    constexpr int F     = (LAYER==1) ? 4   : (LAYER==2) ? 120 : 24;
    constexpr int WTOT  = (LAYER==1) ? 32  : (LAYER==2) ? 832 : 768;
    constexpr int NSLOT = (LAYER==3) ? 32  : 48;
    constexpr int KG    = (THREADS / NSLOT) > 10 ? 10 : (THREADS / NSLOT);
    constexpr int MF    = HH * F;
    constexpr int FT    = (LAYER==2) ? 12 : (LAYER==3) ? 8 : 4;
    constexpr int NFG   = F / FT;
    constexpr int NCT   = 50 * NFG;         // k-groups(2) x f-groups

    extern __shared__ float sm[];
    float* h2s  = sm;                        // 1600
    float* zs   = h2s + 16*HH;               // 16*F
    float* Ms   = zs + 16*F;                 // NPC*MF
    float* part = Ms + NPC*MF;               // KG*NSLOT*NPC
    float* gsm  = part + KG*NSLOT*NPC;       // NPC*8

    const int tid = threadIdx.x;
    const int nbase = blockIdx.x * NPC;

    const float* __restrict__ f0in = (LAYER==2) ? g_f0a : g_f0b;
    const float* __restrict__ f1in = (LAYER==2) ? g_f1a : g_f1b;
    float* f0out = (LAYER==2) ? g_f0b : g_f0a;
    float* f1out = (LAYER==2) ? g_f1b : g_f1a;

    for (int p = 0; p < NPC; p++) {
        int n = nbase + p;
        // ---- Phase A: z features ----
        if (tid < 256) {
            int e = tid >> 4, j = tid & 15;
            int ge = n*KK + e;
            int idx = nbr[ge];
            float u0 = g_u[ge*3+0], u1 = g_u[ge*3+1], u2 = g_u[ge*3+2];
            if (LAYER == 1) {
                if (j == 0) {
                    float g0 = 0.5f * ((float)charges[idx] / 94.0f - 0.5f);
                    zs[e*F+0] = g0;
                    zs[e*F+1] = g0*u0; zs[e*F+2] = g0*u1; zs[e*F+3] = g0*u2;
                }
            } else {
                float g0j = 0.5f * f0in[idx*16 + j];
                zs[e*F + j] = g0j;
                if (LAYER == 2) {
                    zs[e*F + 24 + 0*32 + j] = g0j*u0;
                    zs[e*F + 24 + 1*32 + j] = g0j*u1;
                    zs[e*F + 24 + 2*32 + j] = g0j*u2;
                }
                if (j < 8) {
                    float a = 0.5f * f1in[idx*24 + j*3 + 0];
                    float b = 0.5f * f1in[idx*24 + j*3 + 1];
                    float c = 0.5f * f1in[idx*24 + j*3 + 2];
                    zs[e*F + 16 + j] = a*u0 + b*u1 + c*u2;
                    if (LAYER == 2) {
                        zs[e*F + 24 + 0*32 + 16 + j] = a;
                        zs[e*F + 24 + 1*32 + 16 + j] = b;
                        zs[e*F + 24 + 2*32 + 16 + j] = c;
                        zs[e*F + 24 + 0*32 + 24 + j] = b*u2 - c*u1;
                        zs[e*F + 24 + 1*32 + 24 + j] = c*u0 - a*u2;
                        zs[e*F + 24 + 2*32 + 24 + j] = a*u1 - b*u0;
                    }
                }
            }
        }
        // ---- Phase B: stage h2 tile (float4) ----
        {
            const float4* src = (const float4*)(h2 + (size_t)n*KK*HH);
            float4* dst = (float4*)h2s;
            for (int i = tid; i < 400; i += THREADS) dst[i] = src[i];
        }
        __syncthreads();
        // ---- Phase C: M[k,f] register-tiled (2k x FT) ----
        float* Mp = Ms + p*MF;
        if (tid < NCT) {
            int kg = tid / NFG, fg = tid - kg*NFG;
            int k0 = kg*2, f0 = fg*FT;
            float accm0[FT] = {}, accm1[FT] = {};
            #pragma unroll 4
            for (int e = 0; e < 16; e++) {
                float2 hv = *(const float2*)&h2s[e*HH + k0];
                float zv[FT];
                #pragma unroll
                for (int q = 0; q < FT; q += 4) {
                    float4 z4 = *(const float4*)&zs[e*F + f0 + q];
                    zv[q]=z4.x; zv[q+1]=z4.y; zv[q+2]=z4.z; zv[q+3]=z4.w;
                }
                #pragma unroll
                for (int ff = 0; ff < FT; ff++) {
                    accm0[ff] += hv.x * zv[ff];
                    accm1[ff] += hv.y * zv[ff];
                }
            }
            #pragma unroll
            for (int q = 0; q < FT; q += 4) {
                *(float4*)&Mp[k0*F + f0 + q]     = make_float4(accm0[q],accm0[q+1],accm0[q+2],accm0[q+3]);
                *(float4*)&Mp[(k0+1)*F + f0 + q] = make_float4(accm1[q],accm1[q+1],accm1[q+2],accm1[q+3]);
            }
        }
        __syncthreads();
    }

    // ---- Phase D: contraction, w3 in registers, vectorized M loads ----
    if (tid < KG*NSLOT) {
        int s = tid % NSLOT, g = tid / NSLOT;
        float acc[NPC];
        #pragma unroll
        for (int p = 0; p < NPC; p++) acc[p] = 0.f;

        for (int k = g; k < HH; k += KG) {
            const float* wr = w3r + k*WTOT;
            if (LAYER == 1) {
                if (s < 24) {
                    float wv = wr[s];
                    #pragma unroll
                    for (int p = 0; p < NPC; p++) acc[p] += wv * Ms[p*MF + k*F + 0];
                } else {
                    int q = s - 24, o = q/3, c = q - o*3;
                    float wv = wr[24 + o];
                    #pragma unroll
                    for (int p = 0; p < NPC; p++) acc[p] += wv * Ms[p*MF + k*F + 1 + c];
                }
            } else if (LAYER == 2) {
                if (s < 24) {
                    float w0[16], w1_[8];
                    #pragma unroll
                    for (int i = 0; i < 16; i++) w0[i] = wr[i*24 + s];
                    #pragma unroll
                    for (int i = 0; i < 8; i++)  w1_[i] = wr[384 + i*24 + s];
                    #pragma unroll
                    for (int p = 0; p < NPC; p++) {
                        const float* Mk = Ms + p*MF + k*F;
                        float4 a0=*(const float4*)(Mk),    a1=*(const float4*)(Mk+4);
                        float4 a2=*(const float4*)(Mk+8),  a3=*(const float4*)(Mk+12);
                        float4 b0=*(const float4*)(Mk+16), b1=*(const float4*)(Mk+20);
                        acc[p]+=w0[0]*a0.x;  acc[p]+=w0[1]*a0.y;  acc[p]+=w0[2]*a0.z;  acc[p]+=w0[3]*a0.w;
                        acc[p]+=w0[4]*a1.x;  acc[p]+=w0[5]*a1.y;  acc[p]+=w0[6]*a1.z;  acc[p]+=w0[7]*a1.w;
                        acc[p]+=w0[8]*a2.x;  acc[p]+=w0[9]*a2.y;  acc[p]+=w0[10]*a2.z; acc[p]+=w0[11]*a2.w;
                        acc[p]+=w0[12]*a3.x; acc[p]+=w0[13]*a3.y; acc[p]+=w0[14]*a3.z; acc[p]+=w0[15]*a3.w;
                        acc[p]+=w1_[0]*b0.x; acc[p]+=w1_[1]*b0.y; acc[p]+=w1_[2]*b0.z; acc[p]+=w1_[3]*b0.w;
                        acc[p]+=w1_[4]*b1.x; acc[p]+=w1_[5]*b1.y; acc[p]+=w1_[6]*b1.z; acc[p]+=w1_[7]*b1.w;
                    }
                } else {
                    int q = s - 24, o = q/3, c = q - o*3;
                    float wv0[16], wv1[8], wv2[8];
                    #pragma unroll
                    for (int i = 0; i < 16; i++) wv0[i] = wr[576 + i*8 + o];
                    #pragma unroll
                    for (int i = 0; i < 8; i++)  wv1[i] = wr[704 + i*8 + o];
                    #pragma unroll
                    for (int i = 0; i < 8; i++)  wv2[i] = wr[768 + i*8 + o];
                    #pragma unroll
                    for (int p = 0; p < NPC; p++) {
                        const float* Mk = Ms + p*MF + k*F + 24 + c*32;
                        float4 a0=*(const float4*)(Mk),    a1=*(const float4*)(Mk+4);
                        float4 a2=*(const float4*)(Mk+8),  a3=*(const float4*)(Mk+12);
                        float4 b0=*(const float4*)(Mk+16), b1=*(const float4*)(Mk+20);
                        float4 c0=*(const float4*)(Mk+24), c1=*(const float4*)(Mk+28);
                        acc[p]+=wv0[0]*a0.x;  acc[p]+=wv0[1]*a0.y;  acc[p]+=wv0[2]*a0.z;  acc[p]+=wv0[3]*a0.w;
                        acc[p]+=wv0[4]*a1.x;  acc[p]+=wv0[5]*a1.y;  acc[p]+=wv0[6]*a1.z;  acc[p]+=wv0[7]*a1.w;
                        acc[p]+=wv0[8]*a2.x;  acc[p]+=wv0[9]*a2.y;  acc[p]+=wv0[10]*a2.z; acc[p]+=wv0[11]*a2.w;
                        acc[p]+=wv0[12]*a3.x; acc[p]+=wv0[13]*a3.y; acc[p]+=wv0[14]*a3.z; acc[p]+=wv0[15]*a3.w;
                        acc[p]+=wv1[0]*b0.x;  acc[p]+=wv1[1]*b0.y;  acc[p]+=wv1[2]*b0.z;  acc[p]+=wv1[3]*b0.w;
                        acc[p]+=wv1[4]*b1.x;  acc[p]+=wv1[5]*b1.y;  acc[p]+=wv1[6]*b1.z;  acc[p]+=wv1[7]*b1.w;
                        acc[p]+=wv2[0]*c0.x;  acc[p]+=wv2[1]*c0.y;  acc[p]+=wv2[2]*c0.z;  acc[p]+=wv2[3]*c0.w;
                        acc[p]+=wv2[4]*c1.x;  acc[p]+=wv2[5]*c1.y;  acc[p]+=wv2[6]*c1.z;  acc[p]+=wv2[7]*c1.w;
                    }
                }
            } else {
                float w0[16], w1_[8];
                #pragma unroll
                for (int i = 0; i < 16; i++) w0[i] = wr[i*32 + s];
                #pragma unroll
                for (int i = 0; i < 8; i++)  w1_[i] = wr[512 + i*32 + s];
                #pragma unroll
                for (int p = 0; p < NPC; p++) {
                    const float* Mk = Ms + p*MF + k*F;
                    float4 a0=*(const float4*)(Mk),    a1=*(const float4*)(Mk+4);
                    float4 a2=*(const float4*)(Mk+8),  a3=*(const float4*)(Mk+12);
                    float4 b0=*(const float4*)(Mk+16), b1=*(const float4*)(Mk+20);
                    acc[p]+=w0[0]*a0.x;  acc[p]+=w0[1]*a0.y;  acc[p]+=w0[2]*a0.z;  acc[p]+=w0[3]*a0.w;
                    acc[p]+=w0[4]*a1.x;  acc[p]+=w0[5]*a1.y;  acc[p]+=w0[6]*a1.z;  acc[p]+=w0[7]*a1.w;
                    acc[p]+=w0[8]*a2.x;  acc[p]+=w0[9]*a2.y;  acc[p]+=w0[10]*a2.z; acc[p]+=w0[11]*a2.w;
                    acc[p]+=w0[12]*a3.x; acc[p]+=w0[13]*a3.y; acc[p]+=w0[14]*a3.z; acc[p]+=w0[15]*a3.w;
                    acc[p]+=w1_[0]*b0.x; acc[p]+=w1_[1]*b0.y; acc[p]+=w1_[2]*b0.z; acc[p]+=w1_[3]*b0.w;
                    acc[p]+=w1_[4]*b1.x; acc[p]+=w1_[5]*b1.y; acc[p]+=w1_[6]*b1.z; acc[p]+=w1_[7]*b1.w;
                }
            }
        }
        #pragma unroll
        for (int p = 0; p < NPC; p++)
            part[tid*NPC + p] = acc[p];
    }
    __syncthreads();

    // ---- Phase E: reduce k-groups, mean, nonlinearity ----
    for (int t2 = tid; t2 < NPC*NSLOT; t2 += THREADS) {
        int p = t2 / NSLOT, s = t2 % NSLOT;
        float m = 0.f;
        #pragma unroll
        for (int g = 0; g < KG; g++) m += part[(g*NSLOT + s)*NPC + p];
        m *= (1.0f/16.0f);
        int n = nbase + p;
        if (LAYER == 3) {
            f0out[n*32 + s] = fmaxf(m, 0.f);
        } else {
            part[s*NPC + p] = m;
            if (s >= 16 && s < 24)
                gsm[p*8 + (s-16)] = 1.0f / (1.0f + expf(-m));
        }
    }
    if (LAYER != 3) {
        __syncthreads();
        for (int t2 = tid; t2 < NPC*NSLOT; t2 += THREADS) {
            int p = t2 / NSLOT, s = t2 % NSLOT;
            int n = nbase + p;
            float m = part[s*NPC + p];
            if (s < 16) {
                f0out[n*16 + s] = fmaxf(m, 0.f);
            } else if (s >= 24) {
                int q = s - 24, o = q/3, c = q - o*3;
                f1out[(n*8 + o)*3 + c] = m * gsm[p*8 + o];
            }
        }
    }
}

// ---------------- final reduce ----------------
__global__ void reduce_kernel(float* __restrict__ out) {
    __shared__ float red[256];
    int j = blockIdx.x;
    float s = 0.f;
    for (int n = threadIdx.x; n < NN; n += 256) s += g_f0a[n*32 + j];
    red[threadIdx.x] = s;
    __syncthreads();
    for (int w = 128; w > 0; w >>= 1) {
        if (threadIdx.x < w) red[threadIdx.x] += red[threadIdx.x + w];
        __syncthreads();
    }
    if (threadIdx.x == 0) out[j] = red[0] * (1.0f/NN);
}

// ---------------- host ----------------
extern "C" void kernel_launch(void* const* d_in, const int* in_sizes, int n_in,
                              void* d_out, int out_size) {
    const float* radii   = (const float*)d_in[0];
    const int*   nbr     = (const int*)d_in[1];
    const int*   charges = (const int*)d_in[2];

    void* p;
    cudaGetSymbolAddress(&p, g_basis); float* basis = (float*)p;
    cudaGetSymbolAddress(&p, g_h1A);   float* h1A   = (float*)p;
    cudaGetSymbolAddress(&p, g_h2A);   float* h2A   = (float*)p;
    cudaGetSymbolAddress(&p, g_w1tA);  float* w1tA  = (float*)p;
    cudaGetSymbolAddress(&p, g_w2tA);  float* w2tA  = (float*)p;
    cudaGetSymbolAddress(&p, g_w3rA);  float* w3rA  = (float*)p;

    const int smem_bytes = SMEM_FLOATS * 4;
    cudaFuncSetAttribute(gemm_tc<true, 1>, cudaFuncAttributeMaxDynamicSharedMemorySize, smem_bytes);
    cudaFuncSetAttribute(gemm_tc<true, 0>, cudaFuncAttributeMaxDynamicSharedMemorySize, smem_bytes);

    const int ns1 = (1600 + 16*4   + 8*100*4   + 5*48*8  + 64) * 4;
    const int ns2 = (1600 + 16*120 + 2*100*120 + 10*48*2 + 16) * 4;
    const int ns3 = (1600 + 16*24  + 8*100*24  + 8*32*8  + 64) * 4;
    cudaFuncSetAttribute((const void*)node_tp<1,8,256>, cudaFuncAttributeMaxDynamicSharedMemorySize, ns1);
    cudaFuncSetAttribute((const void*)node_tp<2,2,512>, cudaFuncAttributeMaxDynamicSharedMemorySize, ns2);
    cudaFuncSetAttribute((const void*)node_tp<3,8,256>, cudaFuncAttributeMaxDynamicSharedMemorySize, ns3);

    prep_kernel<<<(EE+255)/256, 256>>>(radii);

    prep_weights<<<(198000+255)/256, 256>>>(
        (const float*)d_in[3],  (const float*)d_in[5],  (const float*)d_in[7],
        (const float*)d_in[8],  (const float*)d_in[10], (const float*)d_in[12],
        (const float*)d_in[13], (const float*)d_in[15], (const float*)d_in[17]);

    Bias3 b1 = {{ (const float*)d_in[4],  (const float*)d_in[9],  (const float*)d_in[14] }};
    Bias3 b2 = {{ (const float*)d_in[6],  (const float*)d_in[11], (const float*)d_in[16] }};

    dim3 gridH(1, EE/128, 3);
    gemm_tc<true, 1><<<gridH, 256, smem_bytes>>>(basis, 0,            w1tA, NBP*HH, b1, h1A, (size_t)EE*HH, HH, NBP);
    gemm_tc<true, 0><<<gridH, 256, smem_bytes>>>(h1A, (size_t)EE*HH, w2tA, HH*HH,  b2, h2A, (size_t)EE*HH, HH, HH);

    node_tp<1,8,256><<<NN/8, 256, ns1>>>(nbr, charges, h2A,                     w3rA);
    node_tp<2,2,512><<<NN/2, 512, ns2>>>(nbr, charges, h2A + (size_t)EE*HH,   w3rA + 83200);
    node_tp<3,8,256><<<NN/8, 256, ns3>>>(nbr, charges, h2A + (size_t)2*EE*HH, w3rA + 2*83200);

    reduce_kernel<<<32, 256>>>((float*)d_out);
}

// round 12
// speedup vs baseline: 1.6394x; 1.0113x over previous
#include <cuda_runtime.h>
#include <math.h>
#include <stdint.h>

#define NN 10000
#define KK 16
#define EE (NN*KK)
#define HH 100
#define NB 10
#define NBP 16

// ---------------- scratch ----------------
__device__ float g_basis[EE*NBP];
__device__ float g_u[EE*3];
__device__ float g_h2A[3*EE*HH];
__device__ float g_f0a[NN*32];
__device__ float g_f0b[NN*32];
__device__ float g_f1a[NN*24];
__device__ float g_f1b[NN*24];
__device__ float g_w1tA[3*NBP*HH];
__device__ float g_w2tA[3*HH*HH];
__device__ float g_w3rA[3*83200];

struct Bias3 { const float* b[3]; };

// ---------------- helpers ----------------
__device__ __forceinline__ float f2tf32f(float v) {
    uint32_t r;
    asm("cvt.rna.tf32.f32 %0, %1;" : "=r"(r) : "f"(v));
    return __uint_as_float(r);
}

__device__ __forceinline__ void mma_tf32(float* c, const uint32_t* a, const uint32_t* b) {
    asm volatile("mma.sync.aligned.m16n8k8.row.col.f32.tf32.tf32.f32 "
        "{%0,%1,%2,%3}, {%4,%5,%6,%7}, {%8,%9}, {%0,%1,%2,%3};"
        : "+f"(c[0]), "+f"(c[1]), "+f"(c[2]), "+f"(c[3])
        : "r"(a[0]), "r"(a[1]), "r"(a[2]), "r"(a[3]), "r"(b[0]), "r"(b[1]));
}

__device__ __forceinline__ void cp16(void* dst_smem, const void* src, int bytes) {
    uint32_t d = (uint32_t)__cvta_generic_to_shared(dst_smem);
    asm volatile("cp.async.cg.shared.global [%0], [%1], 16, %2;"
                 :: "r"(d), "l"(src), "r"(bytes));
}

// ---------------- prep ----------------
__global__ void prep_kernel(const float* __restrict__ radii) {
    int e = blockIdx.x*blockDim.x + threadIdx.x;
    if (e >= EE) return;
    float x = radii[e*3+0], y = radii[e*3+1], z = radii[e*3+2];
    float r = sqrtf(x*x + y*y + z*z);
    float inv = 1.0f / (r + 1e-8f);
    g_u[e*3+0] = x*inv; g_u[e*3+1] = y*inv; g_u[e*3+2] = z*inv;
    float rs = r * 1.8f;
    #pragma unroll
    for (int b = 0; b < NBP; b++) {
        float v = 0.f;
        if (b < NB) {
            float d = rs - (float)b;
            if (fabsf(d) < 1.0f) {
                float c = cospif(0.5f * d);
                v = f2tf32f(c * c);
            }
        }
        g_basis[e*NBP + b] = v;
    }
}

// ---------------- fused weight prep (unchanged from R11) ----------------
__global__ void prep_weights(
    const float* __restrict__ w1a, const float* __restrict__ w2a, const float* __restrict__ w3a,
    const float* __restrict__ w1b, const float* __restrict__ w2b, const float* __restrict__ w3b,
    const float* __restrict__ w1c, const float* __restrict__ w2c, const float* __restrict__ w3c) {
    int i = blockIdx.x*blockDim.x + threadIdx.x;
    if (i < 4800) {
        int l = i / 1600, r = i - l*1600;
        int row = r / HH;
        const float* s = (l==0) ? w1a : (l==1) ? w1b : w1c;
        g_w1tA[i] = (row < NB) ? f2tf32f(s[r]) : 0.f;
    } else if (i < 34800) {
        int j = i - 4800;
        int l = j / 10000, r = j - l*10000;
        const float* s = (l==0) ? w2a : (l==1) ? w2b : w2c;
        g_w2tA[j] = f2tf32f(s[r]);
    } else {
        int j = i - 34800;
        if (j < 3200) {
            g_w3rA[j] = w3a[j];
        } else if (j < 3200 + 83200) {
            int r = j - 3200;
            int k = r / 832, d = r - k*832;
            int src;
            if      (d < 384) { int o=d%24,      i2=d/24;       src = o*16 + i2; }
            else if (d < 576) { int t=d-384; int o=t%24, i2=t/24; src = 384 + o*8 + i2; }
            else if (d < 704) { int t=d-576; int o=t%8,  i2=t/8;  src = 576 + o*16 + i2; }
            else if (d < 768) { int t=d-704; int o=t%8,  i2=t/8;  src = 704 + o*8 + i2; }
            else              { int t=d-768; int o=t%8,  i2=t/8;  src = 768 + o*8 + i2; }
            g_w3rA[83200 + r] = w3b[k*832 + src];
        } else if (j < 3200 + 83200 + 76800) {
            int r = j - 3200 - 83200;
            int k = r / 768, d = r - k*768;
            int src;
            if (d < 512) { int o=d%32, i2=d/32; src = o*16 + i2; }
            else         { int t=d-512; int o=t%32, i2=t/32; src = 512 + o*8 + i2; }
            g_w3rA[2*83200 + r] = w3c[k*768 + src];
        }
    }
}

// ---------------- fused radial MLP: basis -> h1 (smem) -> h2, one kernel ----------------
// CTA = 256 edges, 512 threads = 16 warps (4m x 4n), warp tile 64x32.
// Stage 1: h1 = tf32(relu(basis @ w1 + b1)), kept in smem (pad cols 100..103 = 0).
// Stage 2: h2 = relu(h1 @ w2 + b2) -> global. Same mma k8 order as the split
// kernels => bitwise-identical h2.
#define FAS_S 20
#define FB1_S 136
#define FHS_S 104
#define FB2_S 136
#define FM_SMEM_FLOATS (256*FAS_S + 16*FB1_S + 256*FHS_S + 104*FB2_S)

__global__ void __launch_bounds__(512, 1)
fused_mlp(const float* __restrict__ basis,
          const float* __restrict__ w1A, const float* __restrict__ w2A,
          Bias3 b1, Bias3 b2,
          float* __restrict__ h2A) {
    extern __shared__ float smem[];
    float* As  = smem;                  // 256 x 20  (basis tile)
    float* Bs1 = As + 256*FAS_S;        // 16 x 136  (w1)
    float* Hs  = Bs1 + 16*FB1_S;        // 256 x 104 (h1 tile)
    float* Bs2 = Hs + 256*FHS_S;        // 104 x 136 (w2, rows 100..103 zero)

    const int z = blockIdx.z;
    const float* w1 = w1A + z*NBP*HH;
    const float* w2 = w2A + z*HH*HH;
    const float* bias1 = b1.b[z];
    const float* bias2 = b2.b[z];
    float* C = h2A + (size_t)z*EE*HH;

    const int tid = threadIdx.x;
    const int lane = tid & 31, wid = tid >> 5;
    const int wm = (wid & 3) * 64;
    const int wn = (wid >> 2) * 32;
    const int m0 = blockIdx.y * 256;
    const int gr = lane >> 2, tg = lane & 3;

    // ---- fills (cp.async) ----
    #pragma unroll
    for (int j = 0; j < 2; j++) {                       // As: 256x16
        int c = tid + j*512;
        int row = c >> 2, kch = (c & 3) * 4;
        cp16(As + row*FAS_S + kch, basis + (size_t)(m0+row)*NBP + kch, 16);
    }
    {                                                    // Bs1: 16x128 (zero-pad n>=100)
        int k = tid >> 5, nch = (tid & 31) * 4;
        int bytes = (HH - nch) * 4;
        bytes = bytes < 0 ? 0 : (bytes > 16 ? 16 : bytes);
        const float* src = bytes ? (w1 + k*HH + nch) : w1;
        cp16(Bs1 + k*FB1_S + nch, src, bytes);
    }
    #pragma unroll
    for (int j = 0; j < 7; j++) {                       // Bs2: 104x128 (zero rows>=100, cols>=100)
        int c = tid + j*512;
        if (c < 3328) {
            int k = c >> 5, nch = (c & 31) * 4;
            int bytes = 0;
            if (k < HH) {
                bytes = (HH - nch) * 4;
                bytes = bytes < 0 ? 0 : (bytes > 16 ? 16 : bytes);
            }
            const float* src = bytes ? (w2 + k*HH + nch) : w2;
            cp16(Bs2 + k*FB2_S + nch, src, bytes);
        }
    }
    asm volatile("cp.async.commit_group;");
    // zero Hs pad cols 100..103 (no dependence on the async fills)
    for (int r = tid; r < 256; r += 512) {
        Hs[r*FHS_S + 100] = 0.f; Hs[r*FHS_S + 101] = 0.f;
        Hs[r*FHS_S + 102] = 0.f; Hs[r*FHS_S + 103] = 0.f;
    }
    asm volatile("cp.async.wait_group 0;");
    __syncthreads();

    float acc[4][4][4] = {};

    // ---- Stage 1: K=16 (2 k8 steps) ----
    #pragma unroll
    for (int k8 = 0; k8 < 2; k8++) {
        int k0 = k8 * 8;
        uint32_t a[4][4], b[4][2];
        #pragma unroll
        for (int t2 = 0; t2 < 4; t2++) {
            int row = wm + t2*16 + gr;
            a[t2][0] = __float_as_uint(As[row*FAS_S     + k0 + tg]);
            a[t2][1] = __float_as_uint(As[(row+8)*FAS_S + k0 + tg]);
            a[t2][2] = __float_as_uint(As[row*FAS_S     + k0 + 4 + tg]);
            a[t2][3] = __float_as_uint(As[(row+8)*FAS_S + k0 + 4 + tg]);
        }
        #pragma unroll
        for (int j = 0; j < 4; j++) {
            int col = wn + j*8 + gr;
            b[j][0] = __float_as_uint(Bs1[(k0 + tg)*FB1_S     + col]);
            b[j][1] = __float_as_uint(Bs1[(k0 + 4 + tg)*FB1_S + col]);
        }
        #pragma unroll
        for (int t2 = 0; t2 < 4; t2++)
            #pragma unroll
            for (int j = 0; j < 4; j++)
                mma_tf32(acc[t2][j], a[t2], b[j]);
    }

    // ---- epilogue 1: h1 -> Hs (bias + relu + tf32 round), reset acc ----
    #pragma unroll
    for (int t2 = 0; t2 < 4; t2++) {
        #pragma unroll
        for (int j = 0; j < 4; j++) {
            #pragma unroll
            for (int h = 0; h < 2; h++) {
                int row = wm + t2*16 + gr + h*8;
                #pragma unroll
                for (int q = 0; q < 2; q++) {
                    int cn = wn + j*8 + tg*2 + q;
                    if (cn < HH) {
                        float v = fmaxf(acc[t2][j][h*2 + q] + bias1[cn], 0.f);
                        Hs[row*FHS_S + cn] = f2tf32f(v);
                    }
                }
            }
            #pragma unroll
            for (int q = 0; q < 4; q++) acc[t2][j][q] = 0.f;
        }
    }
    __syncthreads();

    // ---- Stage 2: K=100 padded to 104 (13 k8 steps) ----
    #pragma unroll
    for (int k8 = 0; k8 < 13; k8++) {
        int k0 = k8 * 8;
        uint32_t a[4][4], b[4][2];
        #pragma unroll
        for (int t2 = 0; t2 < 4; t2++) {
            int row = wm + t2*16 + gr;
            a[t2][0] = __float_as_uint(Hs[row*FHS_S     + k0 + tg]);
            a[t2][1] = __float_as_uint(Hs[(row+8)*FHS_S + k0 + tg]);
            a[t2][2] = __float_as_uint(Hs[row*FHS_S     + k0 + 4 + tg]);
            a[t2][3] = __float_as_uint(Hs[(row+8)*FHS_S + k0 + 4 + tg]);
        }
        #pragma unroll
        for (int j = 0; j < 4; j++) {
            int col = wn + j*8 + gr;
            b[j][0] = __float_as_uint(Bs2[(k0 + tg)*FB2_S     + col]);
            b[j][1] = __float_as_uint(Bs2[(k0 + 4 + tg)*FB2_S + col]);
        }
        #pragma unroll
        for (int t2 = 0; t2 < 4; t2++)
            #pragma unroll
            for (int j = 0; j < 4; j++)
                mma_tf32(acc[t2][j], a[t2], b[j]);
    }

    // ---- epilogue 2: h2 -> global (bias + relu, fp32) ----
    #pragma unroll
    for (int t2 = 0; t2 < 4; t2++) {
        #pragma unroll
        for (int j = 0; j < 4; j++) {
            #pragma unroll
            for (int h = 0; h < 2; h++) {
                int row = m0 + wm + t2*16 + gr + h*8;
                #pragma unroll
                for (int q = 0; q < 2; q++) {
                    int cn = wn + j*8 + tg*2 + q;
                    if (cn < HH)
                        C[(size_t)row*HH + cn] = fmaxf(acc[t2][j][h*2 + q] + bias2[cn], 0.f);
                }
            }
        }
    }
}

// ---------------- multi-node fused TP (unchanged from R11) ----------------
template<int LAYER, int NPC, int THREADS>
__global__ void __launch_bounds__(THREADS)
node_tp(const int* __restrict__ nbr, const int* __restrict__ charges,
        const float* __restrict__ h2, const float* __restrict__ w3r) {
    constexpr int F     = (LAYER==1) ? 4   : (LAYER==2) ? 120 : 24;
    constexpr int WTOT  = (LAYER==1) ? 32  : (LAYER==2) ? 832 : 768;
    constexpr int NSLOT = (LAYER==3) ? 32  : 48;
    constexpr int KG    = (THREADS / NSLOT) > 10 ? 10 : (THREADS / NSLOT);
    constexpr int MF    = HH * F;
    constexpr int FT    = (LAYER==2) ? 12 : (LAYER==3) ? 8 : 4;
    constexpr int NFG   = F / FT;
    constexpr int NCT   = 50 * NFG;

    extern __shared__ float sm[];
    float* h2s  = sm;
    float* zs   = h2s + 16*HH;
    float* Ms   = zs + 16*F;
    float* part = Ms + NPC*MF;
    float* gsm  = part + KG*NSLOT*NPC;

    const int tid = threadIdx.x;
    const int nbase = blockIdx.x * NPC;

    const float* __restrict__ f0in = (LAYER==2) ? g_f0a : g_f0b;
    const float* __restrict__ f1in = (LAYER==2) ? g_f1a : g_f1b;
    float* f0out = (LAYER==2) ? g_f0b : g_f0a;
    float* f1out = (LAYER==2) ? g_f1b : g_f1a;

    for (int p = 0; p < NPC; p++) {
        int n = nbase + p;
        if (tid < 256) {
            int e = tid >> 4, j = tid & 15;
            int ge = n*KK + e;
            int idx = nbr[ge];
            float u0 = g_u[ge*3+0], u1 = g_u[ge*3+1], u2 = g_u[ge*3+2];
            if (LAYER == 1) {
                if (j == 0) {
                    float g0 = 0.5f * ((float)charges[idx] / 94.0f - 0.5f);
                    zs[e*F+0] = g0;
                    zs[e*F+1] = g0*u0; zs[e*F+2] = g0*u1; zs[e*F+3] = g0*u2;
                }
            } else {
                float g0j = 0.5f * f0in[idx*16 + j];
                zs[e*F + j] = g0j;
                if (LAYER == 2) {
                    zs[e*F + 24 + 0*32 + j] = g0j*u0;
                    zs[e*F + 24 + 1*32 + j] = g0j*u1;
                    zs[e*F + 24 + 2*32 + j] = g0j*u2;
                }
                if (j < 8) {
                    float a = 0.5f * f1in[idx*24 + j*3 + 0];
                    float b = 0.5f * f1in[idx*24 + j*3 + 1];
                    float c = 0.5f * f1in[idx*24 + j*3 + 2];
                    zs[e*F + 16 + j] = a*u0 + b*u1 + c*u2;
                    if (LAYER == 2) {
                        zs[e*F + 24 + 0*32 + 16 + j] = a;
                        zs[e*F + 24 + 1*32 + 16 + j] = b;
                        zs[e*F + 24 + 2*32 + 16 + j] = c;
                        zs[e*F + 24 + 0*32 + 24 + j] = b*u2 - c*u1;
                        zs[e*F + 24 + 1*32 + 24 + j] = c*u0 - a*u2;
                        zs[e*F + 24 + 2*32 + 24 + j] = a*u1 - b*u0;
                    }
                }
            }
        }
        {
            const float4* src = (const float4*)(h2 + (size_t)n*KK*HH);
            float4* dst = (float4*)h2s;
            for (int i = tid; i < 400; i += THREADS) dst[i] = src[i];
        }
        __syncthreads();
        float* Mp = Ms + p*MF;
        if (tid < NCT) {
            int kg = tid / NFG, fg = tid - kg*NFG;
            int k0 = kg*2, f0 = fg*FT;
            float accm0[FT] = {}, accm1[FT] = {};
            #pragma unroll 4
            for (int e = 0; e < 16; e++) {
                float2 hv = *(const float2*)&h2s[e*HH + k0];
                float zv[FT];
                #pragma unroll
                for (int q = 0; q < FT; q += 4) {
                    float4 z4 = *(const float4*)&zs[e*F + f0 + q];
                    zv[q]=z4.x; zv[q+1]=z4.y; zv[q+2]=z4.z; zv[q+3]=z4.w;
                }
                #pragma unroll
                for (int ff = 0; ff < FT; ff++) {
                    accm0[ff] += hv.x * zv[ff];
                    accm1[ff] += hv.y * zv[ff];
                }
            }
            #pragma unroll
            for (int q = 0; q < FT; q += 4) {
                *(float4*)&Mp[k0*F + f0 + q]     = make_float4(accm0[q],accm0[q+1],accm0[q+2],accm0[q+3]);
                *(float4*)&Mp[(k0+1)*F + f0 + q] = make_float4(accm1[q],accm1[q+1],accm1[q+2],accm1[q+3]);
            }
        }
        __syncthreads();
    }

    if (tid < KG*NSLOT) {
        int s = tid % NSLOT, g = tid / NSLOT;
        float acc[NPC];
        #pragma unroll
        for (int p = 0; p < NPC; p++) acc[p] = 0.f;

        for (int k = g; k < HH; k += KG) {
            const float* wr = w3r + k*WTOT;
            if (LAYER == 1) {
                if (s < 24) {
                    float wv = wr[s];
                    #pragma unroll
                    for (int p = 0; p < NPC; p++) acc[p] += wv * Ms[p*MF + k*F + 0];
                } else {
                    int q = s - 24, o = q/3, c = q - o*3;
                    float wv = wr[24 + o];
                    #pragma unroll
                    for (int p = 0; p < NPC; p++) acc[p] += wv * Ms[p*MF + k*F + 1 + c];
                }
            } else if (LAYER == 2) {
                if (s < 24) {
                    float w0[16], w1_[8];
                    #pragma unroll
                    for (int i = 0; i < 16; i++) w0[i] = wr[i*24 + s];
                    #pragma unroll
                    for (int i = 0; i < 8; i++)  w1_[i] = wr[384 + i*24 + s];
                    #pragma unroll
                    for (int p = 0; p < NPC; p++) {
                        const float* Mk = Ms + p*MF + k*F;
                        float4 a0=*(const float4*)(Mk),    a1=*(const float4*)(Mk+4);
                        float4 a2=*(const float4*)(Mk+8),  a3=*(const float4*)(Mk+12);
                        float4 b0=*(const float4*)(Mk+16), b1=*(const float4*)(Mk+20);
                        acc[p]+=w0[0]*a0.x;  acc[p]+=w0[1]*a0.y;  acc[p]+=w0[2]*a0.z;  acc[p]+=w0[3]*a0.w;
                        acc[p]+=w0[4]*a1.x;  acc[p]+=w0[5]*a1.y;  acc[p]+=w0[6]*a1.z;  acc[p]+=w0[7]*a1.w;
                        acc[p]+=w0[8]*a2.x;  acc[p]+=w0[9]*a2.y;  acc[p]+=w0[10]*a2.z; acc[p]+=w0[11]*a2.w;
                        acc[p]+=w0[12]*a3.x; acc[p]+=w0[13]*a3.y; acc[p]+=w0[14]*a3.z; acc[p]+=w0[15]*a3.w;
                        acc[p]+=w1_[0]*b0.x; acc[p]+=w1_[1]*b0.y; acc[p]+=w1_[2]*b0.z; acc[p]+=w1_[3]*b0.w;
                        acc[p]+=w1_[4]*b1.x; acc[p]+=w1_[5]*b1.y; acc[p]+=w1_[6]*b1.z; acc[p]+=w1_[7]*b1.w;
                    }
                } else {
                    int q = s - 24, o = q/3, c = q - o*3;
                    float wv0[16], wv1[8], wv2[8];
                    #pragma unroll
                    for (int i = 0; i < 16; i++) wv0[i] = wr[576 + i*8 + o];
                    #pragma unroll
                    for (int i = 0; i < 8; i++)  wv1[i] = wr[704 + i*8 + o];
                    #pragma unroll
                    for (int i = 0; i < 8; i++)  wv2[i] = wr[768 + i*8 + o];
                    #pragma unroll
                    for (int p = 0; p < NPC; p++) {
                        const float* Mk = Ms + p*MF + k*F + 24 + c*32;
                        float4 a0=*(const float4*)(Mk),    a1=*(const float4*)(Mk+4);
                        float4 a2=*(const float4*)(Mk+8),  a3=*(const float4*)(Mk+12);
                        float4 b0=*(const float4*)(Mk+16), b1=*(const float4*)(Mk+20);
                        float4 c0=*(const float4*)(Mk+24), c1=*(const float4*)(Mk+28);
                        acc[p]+=wv0[0]*a0.x;  acc[p]+=wv0[1]*a0.y;  acc[p]+=wv0[2]*a0.z;  acc[p]+=wv0[3]*a0.w;
                        acc[p]+=wv0[4]*a1.x;  acc[p]+=wv0[5]*a1.y;  acc[p]+=wv0[6]*a1.z;  acc[p]+=wv0[7]*a1.w;
                        acc[p]+=wv0[8]*a2.x;  acc[p]+=wv0[9]*a2.y;  acc[p]+=wv0[10]*a2.z; acc[p]+=wv0[11]*a2.w;
                        acc[p]+=wv0[12]*a3.x; acc[p]+=wv0[13]*a3.y; acc[p]+=wv0[14]*a3.z; acc[p]+=wv0[15]*a3.w;
                        acc[p]+=wv1[0]*b0.x;  acc[p]+=wv1[1]*b0.y;  acc[p]+=wv1[2]*b0.z;  acc[p]+=wv1[3]*b0.w;
                        acc[p]+=wv1[4]*b1.x;  acc[p]+=wv1[5]*b1.y;  acc[p]+=wv1[6]*b1.z;  acc[p]+=wv1[7]*b1.w;
                        acc[p]+=wv2[0]*c0.x;  acc[p]+=wv2[1]*c0.y;  acc[p]+=wv2[2]*c0.z;  acc[p]+=wv2[3]*c0.w;
                        acc[p]+=wv2[4]*c1.x;  acc[p]+=wv2[5]*c1.y;  acc[p]+=wv2[6]*c1.z;  acc[p]+=wv2[7]*c1.w;
                    }
                }
            } else {
                float w0[16], w1_[8];
                #pragma unroll
                for (int i = 0; i < 16; i++) w0[i] = wr[i*32 + s];
                #pragma unroll
                for (int i = 0; i < 8; i++)  w1_[i] = wr[512 + i*32 + s];
                #pragma unroll
                for (int p = 0; p < NPC; p++) {
                    const float* Mk = Ms + p*MF + k*F;
                    float4 a0=*(const float4*)(Mk),    a1=*(const float4*)(Mk+4);
                    float4 a2=*(const float4*)(Mk+8),  a3=*(const float4*)(Mk+12);
                    float4 b0=*(const float4*)(Mk+16), b1=*(const float4*)(Mk+20);
                    acc[p]+=w0[0]*a0.x;  acc[p]+=w0[1]*a0.y;  acc[p]+=w0[2]*a0.z;  acc[p]+=w0[3]*a0.w;
                    acc[p]+=w0[4]*a1.x;  acc[p]+=w0[5]*a1.y;  acc[p]+=w0[6]*a1.z;  acc[p]+=w0[7]*a1.w;
                    acc[p]+=w0[8]*a2.x;  acc[p]+=w0[9]*a2.y;  acc[p]+=w0[10]*a2.z; acc[p]+=w0[11]*a2.w;
                    acc[p]+=w0[12]*a3.x; acc[p]+=w0[13]*a3.y; acc[p]+=w0[14]*a3.z; acc[p]+=w0[15]*a3.w;
                    acc[p]+=w1_[0]*b0.x; acc[p]+=w1_[1]*b0.y; acc[p]+=w1_[2]*b0.z; acc[p]+=w1_[3]*b0.w;
                    acc[p]+=w1_[4]*b1.x; acc[p]+=w1_[5]*b1.y; acc[p]+=w1_[6]*b1.z; acc[p]+=w1_[7]*b1.w;
                }
            }
        }
        #pragma unroll
        for (int p = 0; p < NPC; p++)
            part[tid*NPC + p] = acc[p];
    }
    __syncthreads();

    for (int t2 = tid; t2 < NPC*NSLOT; t2 += THREADS) {
        int p = t2 / NSLOT, s = t2 % NSLOT;
        float m = 0.f;
        #pragma unroll
        for (int g = 0; g < KG; g++) m += part[(g*NSLOT + s)*NPC + p];
        m *= (1.0f/16.0f);
        int n = nbase + p;
        if (LAYER == 3) {
            f0out[n*32 + s] = fmaxf(m, 0.f);
        } else {
            part[s*NPC + p] = m;
            if (s >= 16 && s < 24)
                gsm[p*8 + (s-16)] = 1.0f / (1.0f + expf(-m));
        }
    }
    if (LAYER != 3) {
        __syncthreads();
        for (int t2 = tid; t2 < NPC*NSLOT; t2 += THREADS) {
            int p = t2 / NSLOT, s = t2 % NSLOT;
            int n = nbase + p;
            float m = part[s*NPC + p];
            if (s < 16) {
                f0out[n*16 + s] = fmaxf(m, 0.f);
            } else if (s >= 24) {
                int q = s - 24, o = q/3, c = q - o*3;
                f1out[(n*8 + o)*3 + c] = m * gsm[p*8 + o];
            }
        }
    }
}

// ---------------- final reduce ----------------
__global__ void reduce_kernel(float* __restrict__ out) {
    __shared__ float red[256];
    int j = blockIdx.x;
    float s = 0.f;
    for (int n = threadIdx.x; n < NN; n += 256) s += g_f0a[n*32 + j];
    red[threadIdx.x] = s;
    __syncthreads();
    for (int w = 128; w > 0; w >>= 1) {
        if (threadIdx.x < w) red[threadIdx.x] += red[threadIdx.x + w];
        __syncthreads();
    }
    if (threadIdx.x == 0) out[j] = red[0] * (1.0f/NN);
}

// ---------------- host ----------------
extern "C" void kernel_launch(void* const* d_in, const int* in_sizes, int n_in,
                              void* d_out, int out_size) {
    const float* radii   = (const float*)d_in[0];
    const int*   nbr     = (const int*)d_in[1];
    const int*   charges = (const int*)d_in[2];

    void* p;
    cudaGetSymbolAddress(&p, g_basis); float* basis = (float*)p;
    cudaGetSymbolAddress(&p, g_h2A);   float* h2A   = (float*)p;
    cudaGetSymbolAddress(&p, g_w1tA);  float* w1tA  = (float*)p;
    cudaGetSymbolAddress(&p, g_w2tA);  float* w2tA  = (float*)p;
    cudaGetSymbolAddress(&p, g_w3rA);  float* w3rA  = (float*)p;

    const int fm_smem = FM_SMEM_FLOATS * 4;   // 192256 B
    cudaFuncSetAttribute(fused_mlp, cudaFuncAttributeMaxDynamicSharedMemorySize, fm_smem);

    const int ns1 = (1600 + 16*4   + 8*100*4   + 5*48*8  + 64) * 4;
    const int ns2 = (1600 + 16*120 + 2*100*120 + 10*48*2 + 16) * 4;
    const int ns3 = (1600 + 16*24  + 8*100*24  + 8*32*8  + 64) * 4;
    cudaFuncSetAttribute((const void*)node_tp<1,8,256>, cudaFuncAttributeMaxDynamicSharedMemorySize, ns1);
    cudaFuncSetAttribute((const void*)node_tp<2,2,512>, cudaFuncAttributeMaxDynamicSharedMemorySize, ns2);
    cudaFuncSetAttribute((const void*)node_tp<3,8,256>, cudaFuncAttributeMaxDynamicSharedMemorySize, ns3);

    prep_kernel<<<(EE+255)/256, 256>>>(radii);

    prep_weights<<<(198000+255)/256, 256>>>(
        (const float*)d_in[3],  (const float*)d_in[5],  (const float*)d_in[7],
        (const float*)d_in[8],  (const float*)d_in[10], (const float*)d_in[12],
        (const float*)d_in[13], (const float*)d_in[15], (const float*)d_in[17]);

    Bias3 b1 = {{ (const float*)d_in[4],  (const float*)d_in[9],  (const float*)d_in[14] }};
    Bias3 b2 = {{ (const float*)d_in[6],  (const float*)d_in[11], (const float*)d_in[16] }};

    dim3 gridF(1, EE/256, 3);
    fused_mlp<<<gridF, 512, fm_smem>>>(basis, w1tA, w2tA, b1, b2, h2A);

    node_tp<1,8,256><<<NN/8, 256, ns1>>>(nbr, charges, h2A,                   w3rA);
    node_tp<2,2,512><<<NN/2, 512, ns2>>>(nbr, charges, h2A + (size_t)EE*HH,   w3rA + 83200);
    node_tp<3,8,256><<<NN/8, 256, ns3>>>(nbr, charges, h2A + (size_t)2*EE*HH, w3rA + 2*83200);

    reduce_kernel<<<32, 256>>>((float*)d_out);
}